// round 13
// baseline (speedup 1.0000x reference)
#include <cuda_runtime.h>
#include <cuda_bf16.h>
#include <cstdint>

#define N_USERS 100000
#define M_ITEMS 200000
#define N_NODES 300000
#define N_EDGES 1200000
#define BATCH   4096

#define TTILE   128
#define ASTRIDE 272                         // bytes per A/W row (136 bf16, pad)
#define WT_BYTES (2 * 64 * ASTRIDE)         // hi+lo W tiles, 34816 B

// ---------------- scratch (device globals: allocation-free rule) -------------
__device__ float4 g_ego0[N_NODES * 16];
__device__ float4 g_ego1[N_NODES * 16];
__device__ float4 g_ego2[N_NODES * 16];
__device__ float4 g_ego3[N_NODES * 16];
__device__ float4 g_side4[N_NODES * 16];
__device__ int    g_deg [N_NODES];
__device__ int    g_ptr [N_NODES];
__device__ int    g_fill[N_NODES];
__device__ int    g_cursor;
__device__ int    g_ccol[N_EDGES];
__device__ float  g_cval[N_EDGES];
__device__ __align__(16) unsigned char g_wt[3][WT_BYTES];
__device__ float  g_bsum[3][64];

// ---------------- helpers ------------------------------------------------------
__device__ __forceinline__ uint32_t s2u(const void* p) {
    return (uint32_t)__cvta_generic_to_shared(p);
}
__device__ __forceinline__ void ldsm4(uint32_t* r, uint32_t a) {
    asm volatile("ldmatrix.sync.aligned.m8n8.x4.shared.b16 {%0,%1,%2,%3}, [%4];"
                 : "=r"(r[0]), "=r"(r[1]), "=r"(r[2]), "=r"(r[3]) : "r"(a));
}
__device__ __forceinline__ void mma_bf16(float* c, const uint32_t* a, const uint32_t* b) {
    asm volatile("mma.sync.aligned.m16n8k16.row.col.f32.bf16.bf16.f32 "
                 "{%0,%1,%2,%3}, {%4,%5,%6,%7}, {%8,%9}, {%0,%1,%2,%3};"
                 : "+f"(c[0]), "+f"(c[1]), "+f"(c[2]), "+f"(c[3])
                 : "r"(a[0]), "r"(a[1]), "r"(a[2]), "r"(a[3]), "r"(b[0]), "r"(b[1]));
}
__device__ __forceinline__ void split2(float a, float b, uint32_t& hi, uint32_t& lo) {
    __nv_bfloat162 h = __floats2bfloat162_rn(a, b);
    float ra = a - __bfloat162float(h.x);
    float rb = b - __bfloat162float(h.y);
    __nv_bfloat162 l = __floats2bfloat162_rn(ra, rb);
    hi = *reinterpret_cast<uint32_t*>(&h);
    lo = *reinterpret_cast<uint32_t*>(&l);
}

// ---------------- init: ego0 = concat(user,item); CSR counters = 0 -------------
__global__ __launch_bounds__(256) void init_kernel(const float4* __restrict__ ue,
                                                   const float4* __restrict__ ie) {
    int i = blockIdx.x * 256 + threadIdx.x;
    if (i < N_NODES) { g_deg[i] = 0; g_fill[i] = 0; }
    if (i == 0) g_cursor = 0;
    if (i >= N_NODES * 16) return;
    g_ego0[i] = (i < N_USERS * 16) ? ue[i] : ie[i - N_USERS * 16];
}

// ---------------- one-time W split: Wt[n][k] hi/lo tiles + bias sums ----------
__global__ __launch_bounds__(256) void prep_w_kernel(const float* __restrict__ W_gc,
                                                     const float* __restrict__ b_gc,
                                                     const float* __restrict__ W_bi,
                                                     const float* __restrict__ b_bi) {
    int layer = blockIdx.x;
    const float* Wgc = W_gc + layer * 4096;
    const float* Wbi = W_bi + layer * 4096;
    int tid = threadIdx.x;
    if (tid < 64) g_bsum[layer][tid] = b_gc[layer * 64 + tid] + b_bi[layer * 64 + tid];
    int n  = tid & 63;
    int ks = (tid >> 6) * 32;
    unsigned char* wh = g_wt[layer] + n * ASTRIDE + ks * 2;
    unsigned char* wl = g_wt[layer] + 64 * ASTRIDE + n * ASTRIDE + ks * 2;
    #pragma unroll
    for (int g = 0; g < 4; ++g) {
        uint32_t hv[4], lv[4];
        #pragma unroll
        for (int p = 0; p < 4; ++p) {
            int k = ks + g * 8 + 2 * p;
            float v0 = (k < 64)     ? __ldg(Wgc + (size_t)k * 64 + n)
                                    : __ldg(Wbi + (size_t)(k - 64) * 64 + n);
            float v1 = (k + 1 < 64) ? __ldg(Wgc + (size_t)(k + 1) * 64 + n)
                                    : __ldg(Wbi + (size_t)(k + 1 - 64) * 64 + n);
            split2(v0, v1, hv[p], lv[p]);
        }
        *(uint4*)(wh + g * 16) = make_uint4(hv[0], hv[1], hv[2], hv[3]);
        *(uint4*)(wl + g * 16) = make_uint4(lv[0], lv[1], lv[2], lv[3]);
    }
}

// ---------------- CSR build ------------------------------------------------------
__global__ __launch_bounds__(256) void hist_kernel(const int* __restrict__ rows) {
    int e = blockIdx.x * 256 + threadIdx.x;
    if (e < N_EDGES) atomicAdd(&g_deg[__ldg(rows + e)], 1);
}

__global__ __launch_bounds__(256) void offset_kernel() {
    int i = blockIdx.x * 256 + threadIdx.x;
    int lane = threadIdx.x & 31;
    int d = (i < N_NODES) ? g_deg[i] : 0;
    int s = d;
    #pragma unroll
    for (int o = 1; o < 32; o <<= 1) {
        int t = __shfl_up_sync(0xffffffffu, s, o);
        if (lane >= o) s += t;
    }
    int total = __shfl_sync(0xffffffffu, s, 31);
    int base = 0;
    if (lane == 31) base = atomicAdd(&g_cursor, total);
    base = __shfl_sync(0xffffffffu, base, 31);
    if (i < N_NODES) g_ptr[i] = base + s - d;
}

__global__ __launch_bounds__(256) void scatter_kernel(const int*   __restrict__ rows,
                                                      const int*   __restrict__ cols,
                                                      const float* __restrict__ vals) {
    int e = blockIdx.x * 256 + threadIdx.x;
    if (e >= N_EDGES) return;
    int r = __ldg(rows + e);
    int pos = g_ptr[r] + atomicAdd(&g_fill[r], 1);
    g_ccol[pos] = __ldg(cols + e);
    g_cval[pos] = __ldg(vals + e);
}

// ---------------- spmm (CSR, warp-per-row, fully predicated 4-batches) ---------
__global__ __launch_bounds__(256) void spmm_csr_kernel(const float4* __restrict__ ego_in) {
    int row  = blockIdx.x * 8 + (threadIdx.x >> 5);
    int lane = threadIdx.x & 31;
    if (row >= N_NODES) return;
    int p = __ldg(&g_ptr[row]);
    int d = __ldg(&g_deg[row]);
    const float2* ego2 = (const float2*)ego_in;

    float2 a0 = make_float2(0.f, 0.f);
    float2 a1 = make_float2(0.f, 0.f);
    if (d > 0) {
        for (int j = 0; j < d; j += 4) {
            int j1 = min(j + 1, d - 1);
            int j2 = min(j + 2, d - 1);
            int j3 = min(j + 3, d - 1);
            int   c0 = __ldg(&g_ccol[p + j]);
            int   c1 = __ldg(&g_ccol[p + j1]);
            int   c2 = __ldg(&g_ccol[p + j2]);
            int   c3 = __ldg(&g_ccol[p + j3]);
            float v0 = __ldg(&g_cval[p + j]);
            float v1 = __ldg(&g_cval[p + j1]);
            float v2 = __ldg(&g_cval[p + j2]);
            float v3 = __ldg(&g_cval[p + j3]);
            if (j + 1 >= d) v1 = 0.f;
            if (j + 2 >= d) v2 = 0.f;
            if (j + 3 >= d) v3 = 0.f;
            float2 x0 = __ldg(ego2 + (size_t)c0 * 32 + lane);
            float2 x1 = __ldg(ego2 + (size_t)c1 * 32 + lane);
            float2 x2 = __ldg(ego2 + (size_t)c2 * 32 + lane);
            float2 x3 = __ldg(ego2 + (size_t)c3 * 32 + lane);
            a0.x += v0 * x0.x; a0.y += v0 * x0.y;
            a1.x += v1 * x1.x; a1.y += v1 * x1.y;
            a0.x += v2 * x2.x; a0.y += v2 * x2.y;
            a1.x += v3 * x3.x; a1.y += v3 * x3.y;
        }
    }
    a0.x += a1.x; a0.y += a1.y;
    ((float2*)g_side4)[(size_t)row * 32 + lane] = a0;
}

// ---------------- transform via mma.sync bf16-split GEMM ----------------------
#define SM_BS   0
#define SM_AH   256
#define SM_AL   (SM_AH + 128 * ASTRIDE)
#define SM_WH   (SM_AL + 128 * ASTRIDE)
#define SM_WL   (SM_WH + 64 * ASTRIDE)
#define SMEM_TR (SM_WL + 64 * ASTRIDE)      // 104704

__global__ __launch_bounds__(256) void transform_kernel(const float4* __restrict__ ego_in,
                                                        float4*       __restrict__ ego_out,
                                                        const unsigned char* __restrict__ wt,
                                                        const float*  __restrict__ bsum) {
    extern __shared__ unsigned char smem[];
    int tid  = threadIdx.x;
    int wid  = tid >> 5;
    int lane = tid & 31;
    int base = blockIdx.x * TTILE;

    // ---- bias sum (precomputed) ----
    if (tid < 64) ((float*)(smem + SM_BS))[tid] = __ldg(bsum + tid);

    // ---- stage W tiles: contiguous uint4 copy of precomputed hi/lo split ----
    {
        const uint4* src = (const uint4*)wt;
        uint4* dst = (uint4*)(smem + SM_WH);
        #pragma unroll
        for (int i = tid; i < WT_BYTES / 16; i += 256) dst[i] = __ldg(src + i);
    }

    // ---- stage A (hi/lo split): thread = (row, half-of-K) ----
    {
        int row  = tid >> 1;
        int half = tid & 1;                  // 0: k 0..63 = S; 1: k 64..127 = E*S
        int n    = base + row;
        const float4* sp = g_side4 + (size_t)n * 16;
        const float4* ep = ego_in  + (size_t)n * 16;
        unsigned char* ah = smem + SM_AH + row * ASTRIDE + half * 128;
        unsigned char* al = smem + SM_AL + row * ASTRIDE + half * 128;
        #pragma unroll
        for (int g = 0; g < 4; ++g) {        // 16 k per chunk
            float x[16];
            if (n < N_NODES) {
                #pragma unroll
                for (int j = 0; j < 4; ++j) {
                    float4 v = __ldg(sp + g * 4 + j);
                    x[4*j] = v.x; x[4*j+1] = v.y; x[4*j+2] = v.z; x[4*j+3] = v.w;
                }
                if (half) {
                    #pragma unroll
                    for (int j = 0; j < 4; ++j) {
                        float4 e = __ldg(ep + g * 4 + j);
                        x[4*j] *= e.x; x[4*j+1] *= e.y; x[4*j+2] *= e.z; x[4*j+3] *= e.w;
                    }
                }
            } else {
                #pragma unroll
                for (int j = 0; j < 16; ++j) x[j] = 0.f;
            }
            uint32_t hv[8], lv[8];
            #pragma unroll
            for (int p = 0; p < 8; ++p) split2(x[2*p], x[2*p+1], hv[p], lv[p]);
            *(uint4*)(ah + g * 32)      = make_uint4(hv[0], hv[1], hv[2], hv[3]);
            *(uint4*)(ah + g * 32 + 16) = make_uint4(hv[4], hv[5], hv[6], hv[7]);
            *(uint4*)(al + g * 32)      = make_uint4(lv[0], lv[1], lv[2], lv[3]);
            *(uint4*)(al + g * 32 + 16) = make_uint4(lv[4], lv[5], lv[6], lv[7]);
        }
    }
    __syncthreads();

    // ---- HMMA mainloop: warp = 16 rows x 64 cols ----
    int m0 = wid * 16;
    uint32_t aAh = s2u(smem + SM_AH) + (m0 + (lane & 15)) * ASTRIDE + ((lane >> 4) * 8) * 2;
    uint32_t aAl = aAh + (SM_AL - SM_AH);
    int bn   = (lane & 7) + ((lane >> 4) & 1) * 8;
    int bk16 = ((lane >> 3) & 1) * 16;
    uint32_t aBh = s2u(smem + SM_WH) + bn * ASTRIDE + bk16;
    uint32_t aBl = aBh + (SM_WL - SM_WH);

    float acc[8][4];
    #pragma unroll
    for (int nt = 0; nt < 8; ++nt)
        #pragma unroll
        for (int j = 0; j < 4; ++j) acc[nt][j] = 0.f;

    #pragma unroll
    for (int kk = 0; kk < 8; ++kk) {
        uint32_t ah[4], al[4];
        ldsm4(ah, aAh + kk * 32);
        ldsm4(al, aAl + kk * 32);
        #pragma unroll
        for (int n2 = 0; n2 < 4; ++n2) {
            uint32_t bh[4], bl[4];
            ldsm4(bh, aBh + n2 * (16 * ASTRIDE) + kk * 32);
            ldsm4(bl, aBl + n2 * (16 * ASTRIDE) + kk * 32);
            mma_bf16(acc[2*n2],     ah, bh);
            mma_bf16(acc[2*n2],     ah, bl);
            mma_bf16(acc[2*n2],     al, bh);
            mma_bf16(acc[2*n2 + 1], ah, bh + 2);
            mma_bf16(acc[2*n2 + 1], ah, bl + 2);
            mma_bf16(acc[2*n2 + 1], al, bh + 2);
        }
    }

    // ---- epilogue in-fragment: bias + LReLU + row-norm; write ego_out ----
    const float* bs = (const float*)(smem + SM_BS);
    int q  = lane & 3;
    int gr = lane >> 2;
    float ss0 = 0.f, ss1 = 0.f;
    #pragma unroll
    for (int nt = 0; nt < 8; ++nt) {
        float b0 = bs[nt * 8 + 2 * q], b1 = bs[nt * 8 + 2 * q + 1];
        float c0 = acc[nt][0] + b0, c1 = acc[nt][1] + b1;
        float c2 = acc[nt][2] + b0, c3 = acc[nt][3] + b1;
        c0 = c0 > 0.f ? c0 : 0.2f * c0;
        c1 = c1 > 0.f ? c1 : 0.2f * c1;
        c2 = c2 > 0.f ? c2 : 0.2f * c2;
        c3 = c3 > 0.f ? c3 : 0.2f * c3;
        ss0 += c0 * c0 + c1 * c1;
        ss1 += c2 * c2 + c3 * c3;
        acc[nt][0] = c0; acc[nt][1] = c1; acc[nt][2] = c2; acc[nt][3] = c3;
    }
    ss0 += __shfl_xor_sync(0xffffffffu, ss0, 1);
    ss0 += __shfl_xor_sync(0xffffffffu, ss0, 2);
    ss1 += __shfl_xor_sync(0xffffffffu, ss1, 1);
    ss1 += __shfl_xor_sync(0xffffffffu, ss1, 2);
    float sc0 = 1.0f / fmaxf(sqrtf(ss0), 1e-12f);
    float sc1 = 1.0f / fmaxf(sqrtf(ss1), 1e-12f);

    int n0 = base + m0 + gr;
    int n1 = n0 + 8;
    float* ego_w = (float*)ego_out;
    #pragma unroll
    for (int nt = 0; nt < 8; ++nt) {
        int col = nt * 8 + 2 * q;
        if (n0 < N_NODES)
            *(float2*)(ego_w + (size_t)n0 * 64 + col) =
                make_float2(acc[nt][0] * sc0, acc[nt][1] * sc0);
        if (n1 < N_NODES)
            *(float2*)(ego_w + (size_t)n1 * 64 + col) =
                make_float2(acc[nt][2] * sc1, acc[nt][3] * sc1);
    }
}

// ---------------- output: dot(sum_k ego_k[u], sum_k ego_k[i]) / 16 ------------
__global__ __launch_bounds__(256) void out_kernel(const int* __restrict__ users,
                                                  const int* __restrict__ items,
                                                  float* __restrict__ out) {
    int b = blockIdx.x * 8 + (threadIdx.x >> 5);
    int lane = threadIdx.x & 31;
    if (b >= BATCH) return;
    size_t u = (size_t)__ldg(users + b) * 64;
    size_t i = ((size_t)N_USERS + __ldg(items + b)) * 64;
    const float* e0 = (const float*)g_ego0;
    const float* e1 = (const float*)g_ego1;
    const float* e2 = (const float*)g_ego2;
    const float* e3 = (const float*)g_ego3;
    float ua = e0[u + lane] + e1[u + lane] + e2[u + lane] + e3[u + lane];
    float ub = e0[u + 32 + lane] + e1[u + 32 + lane] + e2[u + 32 + lane] + e3[u + 32 + lane];
    float ia = e0[i + lane] + e1[i + lane] + e2[i + lane] + e3[i + lane];
    float ib = e0[i + 32 + lane] + e1[i + 32 + lane] + e2[i + 32 + lane] + e3[i + 32 + lane];
    float s = ua * ia + ub * ib;
    #pragma unroll
    for (int o = 16; o > 0; o >>= 1) s += __shfl_xor_sync(0xffffffffu, s, o);
    if (lane == 0) out[b] = s * (1.0f / 16.0f);
}

// ---------------- host launcher ------------------------------------------------
extern "C" void kernel_launch(void* const* d_in, const int* in_sizes, int n_in,
                              void* d_out, int out_size) {
    const int*   users    = (const int*)  d_in[0];
    const int*   items    = (const int*)  d_in[1];
    const int*   rows     = (const int*)  d_in[2];
    const int*   cols     = (const int*)  d_in[3];
    const float* vals     = (const float*)d_in[4];
    const float* user_emb = (const float*)d_in[5];
    const float* item_emb = (const float*)d_in[6];
    const float* W_gc     = (const float*)d_in[7];
    const float* b_gc     = (const float*)d_in[8];
    const float* W_bi     = (const float*)d_in[9];
    const float* b_bi     = (const float*)d_in[10];
    float*       out      = (float*)d_out;

    cudaFuncSetAttribute(transform_kernel,
                         cudaFuncAttributeMaxDynamicSharedMemorySize, SMEM_TR);

    float4* ego[4];
    cudaGetSymbolAddress((void**)&ego[0], g_ego0);
    cudaGetSymbolAddress((void**)&ego[1], g_ego1);
    cudaGetSymbolAddress((void**)&ego[2], g_ego2);
    cudaGetSymbolAddress((void**)&ego[3], g_ego3);
    unsigned char* wt = nullptr;  float* bsum = nullptr;
    cudaGetSymbolAddress((void**)&wt, g_wt);
    cudaGetSymbolAddress((void**)&bsum, g_bsum);

    const int nvec  = N_NODES * 16;
    const int egrid = (N_EDGES + 255) / 256;
    const int ngrid = (N_NODES + 255) / 256;

    init_kernel<<<(nvec + 255) / 256, 256>>>((const float4*)user_emb,
                                             (const float4*)item_emb);
    prep_w_kernel<<<3, 256>>>(W_gc, b_gc, W_bi, b_bi);
    hist_kernel<<<egrid, 256>>>(rows);
    offset_kernel<<<ngrid, 256>>>();
    scatter_kernel<<<egrid, 256>>>(rows, cols, vals);

    const int lgrid = (N_NODES + TTILE - 1) / TTILE;
    const int sgrid = (N_NODES + 7) / 8;
    for (int k = 0; k < 3; ++k) {
        spmm_csr_kernel<<<sgrid, 256>>>(ego[k]);
        transform_kernel<<<lgrid, 256, SMEM_TR>>>(ego[k], ego[k + 1],
            wt + (size_t)k * WT_BYTES, bsum + k * 64);
    }

    out_kernel<<<BATCH / 8, 256>>>(users, items, out);
}

// round 14
// speedup vs baseline: 1.0894x; 1.0894x over previous
#include <cuda_runtime.h>
#include <cuda_fp16.h>
#include <cstdint>

#define N_USERS 100000
#define M_ITEMS 200000
#define N_NODES 300000
#define N_EDGES 1200000
#define BATCH   4096

#define TTILE   128
#define ASTRIDE 272                         // bytes per A/W row (136 fp16, pad)
#define WT_BYTES (2 * 64 * ASTRIDE)         // hi+lo W tiles, 34816 B

// ---------------- scratch (device globals: allocation-free rule) -------------
__device__ float4 g_ego0[N_NODES * 16];
__device__ float4 g_ego1[N_NODES * 16];
__device__ float4 g_ego2[N_NODES * 16];
__device__ float4 g_ego3[N_NODES * 16];
__device__ float4 g_side4[N_NODES * 16];
__device__ int    g_deg [N_NODES];
__device__ int    g_ptr [N_NODES];
__device__ int    g_fill[N_NODES];
__device__ int    g_cursor;
__device__ int    g_ccol[N_EDGES];
__device__ float  g_cval[N_EDGES];
__device__ __align__(16) unsigned char g_wt[3][WT_BYTES];
__device__ float  g_bsum[3][64];

// ---------------- helpers ------------------------------------------------------
__device__ __forceinline__ uint32_t s2u(const void* p) {
    return (uint32_t)__cvta_generic_to_shared(p);
}
__device__ __forceinline__ void ldsm4(uint32_t* r, uint32_t a) {
    asm volatile("ldmatrix.sync.aligned.m8n8.x4.shared.b16 {%0,%1,%2,%3}, [%4];"
                 : "=r"(r[0]), "=r"(r[1]), "=r"(r[2]), "=r"(r[3]) : "r"(a));
}
__device__ __forceinline__ void mma_f16(float* c, const uint32_t* a, const uint32_t* b) {
    asm volatile("mma.sync.aligned.m16n8k16.row.col.f32.f16.f16.f32 "
                 "{%0,%1,%2,%3}, {%4,%5,%6,%7}, {%8,%9}, {%0,%1,%2,%3};"
                 : "+f"(c[0]), "+f"(c[1]), "+f"(c[2]), "+f"(c[3])
                 : "r"(a[0]), "r"(a[1]), "r"(a[2]), "r"(a[3]), "r"(b[0]), "r"(b[1]));
}
// fp16 pack of a float pair (round-to-nearest)
__device__ __forceinline__ uint32_t pack_h2(float a, float b) {
    __half2 h = __floats2half2_rn(a, b);
    return *reinterpret_cast<uint32_t*>(&h);
}
// fp16 hi/lo split of a float pair
__device__ __forceinline__ void split2h(float a, float b, uint32_t& hi, uint32_t& lo) {
    __half2 h = __floats2half2_rn(a, b);
    float ra = a - __half2float(__low2half(h));
    float rb = b - __half2float(__high2half(h));
    __half2 l = __floats2half2_rn(ra, rb);
    hi = *reinterpret_cast<uint32_t*>(&h);
    lo = *reinterpret_cast<uint32_t*>(&l);
}

// ---------------- init: ego0 = concat(user,item); CSR counters = 0 -------------
__global__ __launch_bounds__(256) void init_kernel(const float4* __restrict__ ue,
                                                   const float4* __restrict__ ie) {
    int i = blockIdx.x * 256 + threadIdx.x;
    if (i < N_NODES) { g_deg[i] = 0; g_fill[i] = 0; }
    if (i == 0) g_cursor = 0;
    if (i >= N_NODES * 16) return;
    g_ego0[i] = (i < N_USERS * 16) ? ue[i] : ie[i - N_USERS * 16];
}

// ---------------- one-time W split: Wt[n][k] fp16 hi/lo tiles + bias sums ------
__global__ __launch_bounds__(256) void prep_w_kernel(const float* __restrict__ W_gc,
                                                     const float* __restrict__ b_gc,
                                                     const float* __restrict__ W_bi,
                                                     const float* __restrict__ b_bi) {
    int layer = blockIdx.x;
    const float* Wgc = W_gc + layer * 4096;
    const float* Wbi = W_bi + layer * 4096;
    int tid = threadIdx.x;
    if (tid < 64) g_bsum[layer][tid] = b_gc[layer * 64 + tid] + b_bi[layer * 64 + tid];
    int n  = tid & 63;
    int ks = (tid >> 6) * 32;
    unsigned char* wh = g_wt[layer] + n * ASTRIDE + ks * 2;
    unsigned char* wl = g_wt[layer] + 64 * ASTRIDE + n * ASTRIDE + ks * 2;
    #pragma unroll
    for (int g = 0; g < 4; ++g) {
        uint32_t hv[4], lv[4];
        #pragma unroll
        for (int p = 0; p < 4; ++p) {
            int k = ks + g * 8 + 2 * p;
            float v0 = (k < 64)     ? __ldg(Wgc + (size_t)k * 64 + n)
                                    : __ldg(Wbi + (size_t)(k - 64) * 64 + n);
            float v1 = (k + 1 < 64) ? __ldg(Wgc + (size_t)(k + 1) * 64 + n)
                                    : __ldg(Wbi + (size_t)(k + 1 - 64) * 64 + n);
            split2h(v0, v1, hv[p], lv[p]);
        }
        *(uint4*)(wh + g * 16) = make_uint4(hv[0], hv[1], hv[2], hv[3]);
        *(uint4*)(wl + g * 16) = make_uint4(lv[0], lv[1], lv[2], lv[3]);
    }
}

// ---------------- CSR build ------------------------------------------------------
__global__ __launch_bounds__(256) void hist_kernel(const int* __restrict__ rows) {
    int e = blockIdx.x * 256 + threadIdx.x;
    if (e < N_EDGES) atomicAdd(&g_deg[__ldg(rows + e)], 1);
}

__global__ __launch_bounds__(256) void offset_kernel() {
    int i = blockIdx.x * 256 + threadIdx.x;
    int lane = threadIdx.x & 31;
    int d = (i < N_NODES) ? g_deg[i] : 0;
    int s = d;
    #pragma unroll
    for (int o = 1; o < 32; o <<= 1) {
        int t = __shfl_up_sync(0xffffffffu, s, o);
        if (lane >= o) s += t;
    }
    int total = __shfl_sync(0xffffffffu, s, 31);
    int base = 0;
    if (lane == 31) base = atomicAdd(&g_cursor, total);
    base = __shfl_sync(0xffffffffu, base, 31);
    if (i < N_NODES) g_ptr[i] = base + s - d;
}

__global__ __launch_bounds__(256) void scatter_kernel(const int*   __restrict__ rows,
                                                      const int*   __restrict__ cols,
                                                      const float* __restrict__ vals) {
    int e = blockIdx.x * 256 + threadIdx.x;
    if (e >= N_EDGES) return;
    int r = __ldg(rows + e);
    int pos = g_ptr[r] + atomicAdd(&g_fill[r], 1);
    g_ccol[pos] = __ldg(cols + e);
    g_cval[pos] = __ldg(vals + e);
}

// ---------------- spmm (CSR, warp-per-row, 4-way edge unroll) — R11-proven ------
__global__ __launch_bounds__(256) void spmm_csr_kernel(const float4* __restrict__ ego_in) {
    int row  = blockIdx.x * 8 + (threadIdx.x >> 5);
    int lane = threadIdx.x & 31;
    if (row >= N_NODES) return;
    int p = __ldg(&g_ptr[row]);
    int d = __ldg(&g_deg[row]);
    const float2* ego2 = (const float2*)ego_in;

    float2 a0 = make_float2(0.f, 0.f);
    float2 a1 = make_float2(0.f, 0.f);
    int j = 0;
    for (; j + 4 <= d; j += 4) {
        int   c0 = __ldg(&g_ccol[p + j]);
        int   c1 = __ldg(&g_ccol[p + j + 1]);
        int   c2 = __ldg(&g_ccol[p + j + 2]);
        int   c3 = __ldg(&g_ccol[p + j + 3]);
        float v0 = __ldg(&g_cval[p + j]);
        float v1 = __ldg(&g_cval[p + j + 1]);
        float v2 = __ldg(&g_cval[p + j + 2]);
        float v3 = __ldg(&g_cval[p + j + 3]);
        float2 x0 = __ldg(ego2 + (size_t)c0 * 32 + lane);
        float2 x1 = __ldg(ego2 + (size_t)c1 * 32 + lane);
        float2 x2 = __ldg(ego2 + (size_t)c2 * 32 + lane);
        float2 x3 = __ldg(ego2 + (size_t)c3 * 32 + lane);
        a0.x += v0 * x0.x; a0.y += v0 * x0.y;
        a1.x += v1 * x1.x; a1.y += v1 * x1.y;
        a0.x += v2 * x2.x; a0.y += v2 * x2.y;
        a1.x += v3 * x3.x; a1.y += v3 * x3.y;
    }
    if (j < d) {
        int   c = __ldg(&g_ccol[p + j]);
        float v = __ldg(&g_cval[p + j]);
        for (++j; j <= d; ++j) {
            int   cn = 0; float vn = 0.f;
            if (j < d) { cn = __ldg(&g_ccol[p + j]); vn = __ldg(&g_cval[p + j]); }
            float2 x = __ldg(ego2 + (size_t)c * 32 + lane);
            a0.x += v * x.x; a0.y += v * x.y;
            c = cn; v = vn;
        }
    }
    a0.x += a1.x; a0.y += a1.y;
    ((float2*)g_side4)[(size_t)row * 32 + lane] = a0;
}

// ---------------- transform via mma.sync fp16 GEMM -----------------------------
// A (fp16, single) = [S | E*S]; B (fp16 hi+lo) = [Wgc; Wbi]^T.
// D = Ah@Bh + Ah@Bl. smem 69.9KB -> 3 CTAs/SM.
#define SM_BS   0
#define SM_AH   256
#define SM_WH   (SM_AH + 128 * ASTRIDE)     // 35072
#define SM_WL   (SM_WH + 64 * ASTRIDE)      // 52480
#define SMEM_TR (SM_WL + 64 * ASTRIDE)      // 69888

__global__ __launch_bounds__(256) void transform_kernel(const float4* __restrict__ ego_in,
                                                        float4*       __restrict__ ego_out,
                                                        const unsigned char* __restrict__ wt,
                                                        const float*  __restrict__ bsum) {
    extern __shared__ unsigned char smem[];
    int tid  = threadIdx.x;
    int wid  = tid >> 5;
    int lane = tid & 31;
    int base = blockIdx.x * TTILE;

    // ---- bias sum (precomputed) ----
    if (tid < 64) ((float*)(smem + SM_BS))[tid] = __ldg(bsum + tid);

    // ---- stage W tiles: contiguous uint4 copy of precomputed fp16 hi/lo ----
    {
        const uint4* src = (const uint4*)wt;
        uint4* dst = (uint4*)(smem + SM_WH);
        #pragma unroll
        for (int i = tid; i < WT_BYTES / 16; i += 256) dst[i] = __ldg(src + i);
    }

    // ---- stage A (fp16 single): thread = (row, half-of-K) ----
    {
        int row  = tid >> 1;
        int half = tid & 1;                  // 0: k 0..63 = S; 1: k 64..127 = E*S
        int n    = base + row;
        const float4* sp = g_side4 + (size_t)n * 16;
        const float4* ep = ego_in  + (size_t)n * 16;
        unsigned char* ah = smem + SM_AH + row * ASTRIDE + half * 128;
        #pragma unroll
        for (int g = 0; g < 4; ++g) {        // 16 k per chunk
            float x[16];
            if (n < N_NODES) {
                #pragma unroll
                for (int j = 0; j < 4; ++j) {
                    float4 v = __ldg(sp + g * 4 + j);
                    x[4*j] = v.x; x[4*j+1] = v.y; x[4*j+2] = v.z; x[4*j+3] = v.w;
                }
                if (half) {
                    #pragma unroll
                    for (int j = 0; j < 4; ++j) {
                        float4 e = __ldg(ep + g * 4 + j);
                        x[4*j] *= e.x; x[4*j+1] *= e.y; x[4*j+2] *= e.z; x[4*j+3] *= e.w;
                    }
                }
            } else {
                #pragma unroll
                for (int j = 0; j < 16; ++j) x[j] = 0.f;
            }
            uint32_t hv[8];
            #pragma unroll
            for (int p = 0; p < 8; ++p) hv[p] = pack_h2(x[2*p], x[2*p+1]);
            *(uint4*)(ah + g * 32)      = make_uint4(hv[0], hv[1], hv[2], hv[3]);
            *(uint4*)(ah + g * 32 + 16) = make_uint4(hv[4], hv[5], hv[6], hv[7]);
        }
    }
    __syncthreads();

    // ---- HMMA mainloop: warp = 16 rows x 64 cols, 2 terms (Ah*Bh + Ah*Bl) ----
    int m0 = wid * 16;
    uint32_t aAh = s2u(smem + SM_AH) + (m0 + (lane & 15)) * ASTRIDE + ((lane >> 4) * 8) * 2;
    int bn   = (lane & 7) + ((lane >> 4) & 1) * 8;
    int bk16 = ((lane >> 3) & 1) * 16;
    uint32_t aBh = s2u(smem + SM_WH) + bn * ASTRIDE + bk16;
    uint32_t aBl = aBh + (SM_WL - SM_WH);

    float acc[8][4];
    #pragma unroll
    for (int nt = 0; nt < 8; ++nt)
        #pragma unroll
        for (int j = 0; j < 4; ++j) acc[nt][j] = 0.f;

    #pragma unroll
    for (int kk = 0; kk < 8; ++kk) {
        uint32_t ah[4];
        ldsm4(ah, aAh + kk * 32);
        #pragma unroll
        for (int n2 = 0; n2 < 4; ++n2) {
            uint32_t bh[4], bl[4];
            ldsm4(bh, aBh + n2 * (16 * ASTRIDE) + kk * 32);
            ldsm4(bl, aBl + n2 * (16 * ASTRIDE) + kk * 32);
            mma_f16(acc[2*n2],     ah, bh);
            mma_f16(acc[2*n2],     ah, bl);
            mma_f16(acc[2*n2 + 1], ah, bh + 2);
            mma_f16(acc[2*n2 + 1], ah, bl + 2);
        }
    }

    // ---- epilogue in-fragment: bias + LReLU + row-norm; write ego_out ----
    const float* bs = (const float*)(smem + SM_BS);
    int q  = lane & 3;
    int gr = lane >> 2;
    float ss0 = 0.f, ss1 = 0.f;
    #pragma unroll
    for (int nt = 0; nt < 8; ++nt) {
        float b0 = bs[nt * 8 + 2 * q], b1 = bs[nt * 8 + 2 * q + 1];
        float c0 = acc[nt][0] + b0, c1 = acc[nt][1] + b1;
        float c2 = acc[nt][2] + b0, c3 = acc[nt][3] + b1;
        c0 = c0 > 0.f ? c0 : 0.2f * c0;
        c1 = c1 > 0.f ? c1 : 0.2f * c1;
        c2 = c2 > 0.f ? c2 : 0.2f * c2;
        c3 = c3 > 0.f ? c3 : 0.2f * c3;
        ss0 += c0 * c0 + c1 * c1;
        ss1 += c2 * c2 + c3 * c3;
        acc[nt][0] = c0; acc[nt][1] = c1; acc[nt][2] = c2; acc[nt][3] = c3;
    }
    ss0 += __shfl_xor_sync(0xffffffffu, ss0, 1);
    ss0 += __shfl_xor_sync(0xffffffffu, ss0, 2);
    ss1 += __shfl_xor_sync(0xffffffffu, ss1, 1);
    ss1 += __shfl_xor_sync(0xffffffffu, ss1, 2);
    float sc0 = 1.0f / fmaxf(sqrtf(ss0), 1e-12f);
    float sc1 = 1.0f / fmaxf(sqrtf(ss1), 1e-12f);

    int n0 = base + m0 + gr;
    int n1 = n0 + 8;
    float* ego_w = (float*)ego_out;
    #pragma unroll
    for (int nt = 0; nt < 8; ++nt) {
        int col = nt * 8 + 2 * q;
        if (n0 < N_NODES)
            *(float2*)(ego_w + (size_t)n0 * 64 + col) =
                make_float2(acc[nt][0] * sc0, acc[nt][1] * sc0);
        if (n1 < N_NODES)
            *(float2*)(ego_w + (size_t)n1 * 64 + col) =
                make_float2(acc[nt][2] * sc1, acc[nt][3] * sc1);
    }
}

// ---------------- output: dot(sum_k ego_k[u], sum_k ego_k[i]) / 16 ------------
__global__ __launch_bounds__(256) void out_kernel(const int* __restrict__ users,
                                                  const int* __restrict__ items,
                                                  float* __restrict__ out) {
    int b = blockIdx.x * 8 + (threadIdx.x >> 5);
    int lane = threadIdx.x & 31;
    if (b >= BATCH) return;
    size_t u = (size_t)__ldg(users + b) * 64;
    size_t i = ((size_t)N_USERS + __ldg(items + b)) * 64;
    const float* e0 = (const float*)g_ego0;
    const float* e1 = (const float*)g_ego1;
    const float* e2 = (const float*)g_ego2;
    const float* e3 = (const float*)g_ego3;
    float ua = e0[u + lane] + e1[u + lane] + e2[u + lane] + e3[u + lane];
    float ub = e0[u + 32 + lane] + e1[u + 32 + lane] + e2[u + 32 + lane] + e3[u + 32 + lane];
    float ia = e0[i + lane] + e1[i + lane] + e2[i + lane] + e3[i + lane];
    float ib = e0[i + 32 + lane] + e1[i + 32 + lane] + e2[i + 32 + lane] + e3[i + 32 + lane];
    float s = ua * ia + ub * ib;
    #pragma unroll
    for (int o = 16; o > 0; o >>= 1) s += __shfl_xor_sync(0xffffffffu, s, o);
    if (lane == 0) out[b] = s * (1.0f / 16.0f);
}

// ---------------- host launcher ------------------------------------------------
extern "C" void kernel_launch(void* const* d_in, const int* in_sizes, int n_in,
                              void* d_out, int out_size) {
    const int*   users    = (const int*)  d_in[0];
    const int*   items    = (const int*)  d_in[1];
    const int*   rows     = (const int*)  d_in[2];
    const int*   cols     = (const int*)  d_in[3];
    const float* vals     = (const float*)d_in[4];
    const float* user_emb = (const float*)d_in[5];
    const float* item_emb = (const float*)d_in[6];
    const float* W_gc     = (const float*)d_in[7];
    const float* b_gc     = (const float*)d_in[8];
    const float* W_bi     = (const float*)d_in[9];
    const float* b_bi     = (const float*)d_in[10];
    float*       out      = (float*)d_out;

    cudaFuncSetAttribute(transform_kernel,
                         cudaFuncAttributeMaxDynamicSharedMemorySize, SMEM_TR);

    float4* ego[4];
    cudaGetSymbolAddress((void**)&ego[0], g_ego0);
    cudaGetSymbolAddress((void**)&ego[1], g_ego1);
    cudaGetSymbolAddress((void**)&ego[2], g_ego2);
    cudaGetSymbolAddress((void**)&ego[3], g_ego3);
    unsigned char* wt = nullptr;  float* bsum = nullptr;
    cudaGetSymbolAddress((void**)&wt, g_wt);
    cudaGetSymbolAddress((void**)&bsum, g_bsum);

    const int nvec  = N_NODES * 16;
    const int egrid = (N_EDGES + 255) / 256;
    const int ngrid = (N_NODES + 255) / 256;

    init_kernel<<<(nvec + 255) / 256, 256>>>((const float4*)user_emb,
                                             (const float4*)item_emb);
    prep_w_kernel<<<3, 256>>>(W_gc, b_gc, W_bi, b_bi);
    hist_kernel<<<egrid, 256>>>(rows);
    offset_kernel<<<ngrid, 256>>>();
    scatter_kernel<<<egrid, 256>>>(rows, cols, vals);

    const int lgrid = (N_NODES + TTILE - 1) / TTILE;
    const int sgrid = (N_NODES + 7) / 8;
    for (int k = 0; k < 3; ++k) {
        spmm_csr_kernel<<<sgrid, 256>>>(ego[k]);
        transform_kernel<<<lgrid, 256, SMEM_TR>>>(ego[k], ego[k + 1],
            wt + (size_t)k * WT_BYTES, bsum + k * 64);
    }

    out_kernel<<<BATCH / 8, 256>>>(users, items, out);
}

// round 15
// speedup vs baseline: 1.4061x; 1.2907x over previous
#include <cuda_runtime.h>
#include <cuda_fp16.h>
#include <cstdint>

#define N_USERS 100000
#define M_ITEMS 200000
#define N_NODES 300000
#define N_EDGES 1200000
#define BATCH   4096

#define TTILE   128
#define ASTRIDE 272                         // bytes per A/W row (136 fp16, pad)
#define WT_BYTES (64 * ASTRIDE)             // single-fp16 W tile, 17408 B

// ---------------- scratch (device globals: allocation-free rule) -------------
// ego/side stored as packed half2 (uint32 per 2 features), 32 words/node
__device__ uint32_t g_ego0[N_NODES * 32];
__device__ uint32_t g_ego1[N_NODES * 32];
__device__ uint32_t g_ego2[N_NODES * 32];
__device__ uint32_t g_ego3[N_NODES * 32];
__device__ uint32_t g_sideh[N_NODES * 32];
__device__ int    g_deg [N_NODES];
__device__ int    g_ptr [N_NODES];
__device__ int    g_fill[N_NODES];
__device__ int    g_cursor;
__device__ int    g_ccol[N_EDGES];
__device__ float  g_cval[N_EDGES];
__device__ __align__(16) unsigned char g_wt[3][WT_BYTES];
__device__ float  g_bsum[3][64];

// ---------------- helpers ------------------------------------------------------
__device__ __forceinline__ uint32_t s2u(const void* p) {
    return (uint32_t)__cvta_generic_to_shared(p);
}
__device__ __forceinline__ void ldsm4(uint32_t* r, uint32_t a) {
    asm volatile("ldmatrix.sync.aligned.m8n8.x4.shared.b16 {%0,%1,%2,%3}, [%4];"
                 : "=r"(r[0]), "=r"(r[1]), "=r"(r[2]), "=r"(r[3]) : "r"(a));
}
__device__ __forceinline__ void mma_f16(float* c, const uint32_t* a, const uint32_t* b) {
    asm volatile("mma.sync.aligned.m16n8k16.row.col.f32.f16.f16.f32 "
                 "{%0,%1,%2,%3}, {%4,%5,%6,%7}, {%8,%9}, {%0,%1,%2,%3};"
                 : "+f"(c[0]), "+f"(c[1]), "+f"(c[2]), "+f"(c[3])
                 : "r"(a[0]), "r"(a[1]), "r"(a[2]), "r"(a[3]), "r"(b[0]), "r"(b[1]));
}
__device__ __forceinline__ uint32_t pack_h2(float a, float b) {
    __half2 h = __floats2half2_rn(a, b);
    return *reinterpret_cast<uint32_t*>(&h);
}
__device__ __forceinline__ float2 unpack_h2(uint32_t w) {
    return __half22float2(*reinterpret_cast<__half2*>(&w));
}
__device__ __forceinline__ uint32_t hmul2u(uint32_t a, uint32_t b) {
    __half2 r = __hmul2(*reinterpret_cast<__half2*>(&a), *reinterpret_cast<__half2*>(&b));
    return *reinterpret_cast<uint32_t*>(&r);
}

// ---------------- init: ego0 = fp16(concat(user,item)); CSR counters = 0 -------
__global__ __launch_bounds__(256) void init_kernel(const float4* __restrict__ ue,
                                                   const float4* __restrict__ ie) {
    int i = blockIdx.x * 256 + threadIdx.x;   // one uint4 (8 halfs = 8 floats)
    if (i < N_NODES) { g_deg[i] = 0; g_fill[i] = 0; }
    if (i == 0) g_cursor = 0;
    if (i >= N_NODES * 8) return;
    int node = i >> 3;
    int q    = i & 7;
    const float4* src = (node < N_USERS) ? (ue + (size_t)node * 16 + q * 2)
                                         : (ie + (size_t)(node - N_USERS) * 16 + q * 2);
    float4 v0 = __ldg(src);
    float4 v1 = __ldg(src + 1);
    ((uint4*)g_ego0)[i] = make_uint4(pack_h2(v0.x, v0.y), pack_h2(v0.z, v0.w),
                                     pack_h2(v1.x, v1.y), pack_h2(v1.z, v1.w));
}

// ---------------- one-time W fp16 tile + bias sums ------------------------------
__global__ __launch_bounds__(256) void prep_w_kernel(const float* __restrict__ W_gc,
                                                     const float* __restrict__ b_gc,
                                                     const float* __restrict__ W_bi,
                                                     const float* __restrict__ b_bi) {
    int layer = blockIdx.x;
    const float* Wgc = W_gc + layer * 4096;
    const float* Wbi = W_bi + layer * 4096;
    int tid = threadIdx.x;
    if (tid < 64) g_bsum[layer][tid] = b_gc[layer * 64 + tid] + b_bi[layer * 64 + tid];
    int n  = tid & 63;
    int ks = (tid >> 6) * 32;
    unsigned char* wh = g_wt[layer] + n * ASTRIDE + ks * 2;
    #pragma unroll
    for (int g = 0; g < 4; ++g) {
        uint32_t hv[4];
        #pragma unroll
        for (int p = 0; p < 4; ++p) {
            int k = ks + g * 8 + 2 * p;
            float v0 = (k < 64)     ? __ldg(Wgc + (size_t)k * 64 + n)
                                    : __ldg(Wbi + (size_t)(k - 64) * 64 + n);
            float v1 = (k + 1 < 64) ? __ldg(Wgc + (size_t)(k + 1) * 64 + n)
                                    : __ldg(Wbi + (size_t)(k + 1 - 64) * 64 + n);
            hv[p] = pack_h2(v0, v1);
        }
        *(uint4*)(wh + g * 16) = make_uint4(hv[0], hv[1], hv[2], hv[3]);
    }
}

// ---------------- CSR build ------------------------------------------------------
__global__ __launch_bounds__(256) void hist_kernel(const int* __restrict__ rows) {
    int e = blockIdx.x * 256 + threadIdx.x;
    if (e < N_EDGES) atomicAdd(&g_deg[__ldg(rows + e)], 1);
}

__global__ __launch_bounds__(256) void offset_kernel() {
    int i = blockIdx.x * 256 + threadIdx.x;
    int lane = threadIdx.x & 31;
    int d = (i < N_NODES) ? g_deg[i] : 0;
    int s = d;
    #pragma unroll
    for (int o = 1; o < 32; o <<= 1) {
        int t = __shfl_up_sync(0xffffffffu, s, o);
        if (lane >= o) s += t;
    }
    int total = __shfl_sync(0xffffffffu, s, 31);
    int base = 0;
    if (lane == 31) base = atomicAdd(&g_cursor, total);
    base = __shfl_sync(0xffffffffu, base, 31);
    if (i < N_NODES) g_ptr[i] = base + s - d;
}

__global__ __launch_bounds__(256) void scatter_kernel(const int*   __restrict__ rows,
                                                      const int*   __restrict__ cols,
                                                      const float* __restrict__ vals) {
    int e = blockIdx.x * 256 + threadIdx.x;
    if (e >= N_EDGES) return;
    int r = __ldg(rows + e);
    int pos = g_ptr[r] + atomicAdd(&g_fill[r], 1);
    g_ccol[pos] = __ldg(cols + e);
    g_cval[pos] = __ldg(vals + e);
}

// ---------------- spmm (CSR, warp-per-row, fp16 gather, fp32 accum) -------------
__global__ __launch_bounds__(256) void spmm_csr_kernel(const uint32_t* __restrict__ ego_in) {
    int row  = blockIdx.x * 8 + (threadIdx.x >> 5);
    int lane = threadIdx.x & 31;
    if (row >= N_NODES) return;
    int p = __ldg(&g_ptr[row]);
    int d = __ldg(&g_deg[row]);

    float2 a0 = make_float2(0.f, 0.f);
    float2 a1 = make_float2(0.f, 0.f);
    int j = 0;
    for (; j + 4 <= d; j += 4) {
        int   c0 = __ldg(&g_ccol[p + j]);
        int   c1 = __ldg(&g_ccol[p + j + 1]);
        int   c2 = __ldg(&g_ccol[p + j + 2]);
        int   c3 = __ldg(&g_ccol[p + j + 3]);
        float v0 = __ldg(&g_cval[p + j]);
        float v1 = __ldg(&g_cval[p + j + 1]);
        float v2 = __ldg(&g_cval[p + j + 2]);
        float v3 = __ldg(&g_cval[p + j + 3]);
        float2 x0 = unpack_h2(__ldg(ego_in + (size_t)c0 * 32 + lane));
        float2 x1 = unpack_h2(__ldg(ego_in + (size_t)c1 * 32 + lane));
        float2 x2 = unpack_h2(__ldg(ego_in + (size_t)c2 * 32 + lane));
        float2 x3 = unpack_h2(__ldg(ego_in + (size_t)c3 * 32 + lane));
        a0.x += v0 * x0.x; a0.y += v0 * x0.y;
        a1.x += v1 * x1.x; a1.y += v1 * x1.y;
        a0.x += v2 * x2.x; a0.y += v2 * x2.y;
        a1.x += v3 * x3.x; a1.y += v3 * x3.y;
    }
    if (j < d) {
        int   c = __ldg(&g_ccol[p + j]);
        float v = __ldg(&g_cval[p + j]);
        for (++j; j <= d; ++j) {
            int   cn = 0; float vn = 0.f;
            if (j < d) { cn = __ldg(&g_ccol[p + j]); vn = __ldg(&g_cval[p + j]); }
            float2 x = unpack_h2(__ldg(ego_in + (size_t)c * 32 + lane));
            a0.x += v * x.x; a0.y += v * x.y;
            c = cn; v = vn;
        }
    }
    a0.x += a1.x; a0.y += a1.y;
    g_sideh[(size_t)row * 32 + lane] = pack_h2(a0.x, a0.y);
}

// ---------------- transform via mma.sync fp16 GEMM (single term) ----------------
// A (fp16) = [S | E*S]; B (fp16) = [Wgc; Wbi]^T. smem 52.5KB -> 4 CTAs/SM.
#define SM_BS   0
#define SM_AH   256
#define SM_WH   (SM_AH + 128 * ASTRIDE)     // 35072
#define SMEM_TR (SM_WH + WT_BYTES)          // 52480

__global__ __launch_bounds__(256) void transform_kernel(const uint32_t* __restrict__ ego_in,
                                                        uint32_t*       __restrict__ ego_out,
                                                        const unsigned char* __restrict__ wt,
                                                        const float*  __restrict__ bsum) {
    extern __shared__ unsigned char smem[];
    int tid  = threadIdx.x;
    int wid  = tid >> 5;
    int lane = tid & 31;
    int base = blockIdx.x * TTILE;

    // ---- bias sum (precomputed) ----
    if (tid < 64) ((float*)(smem + SM_BS))[tid] = __ldg(bsum + tid);

    // ---- stage W tile: contiguous uint4 copy ----
    {
        const uint4* src = (const uint4*)wt;
        uint4* dst = (uint4*)(smem + SM_WH);
        #pragma unroll
        for (int i = tid; i < WT_BYTES / 16; i += 256) dst[i] = __ldg(src + i);
    }

    // ---- stage A: thread = (row, half). half0: copy S; half1: E*S (hmul2) ----
    {
        int row  = tid >> 1;
        int half = tid & 1;
        int n    = base + row;
        unsigned char* dst = smem + SM_AH + row * ASTRIDE + half * 128;
        if (n < N_NODES) {
            const uint4* sp = (const uint4*)(g_sideh + (size_t)n * 32);
            if (half == 0) {
                #pragma unroll
                for (int g = 0; g < 8; ++g) *(uint4*)(dst + g * 16) = __ldg(sp + g);
            } else {
                const uint4* ep = (const uint4*)(ego_in + (size_t)n * 32);
                #pragma unroll
                for (int g = 0; g < 8; ++g) {
                    uint4 s = __ldg(sp + g);
                    uint4 e = __ldg(ep + g);
                    *(uint4*)(dst + g * 16) = make_uint4(hmul2u(s.x, e.x), hmul2u(s.y, e.y),
                                                         hmul2u(s.z, e.z), hmul2u(s.w, e.w));
                }
            }
        } else {
            #pragma unroll
            for (int g = 0; g < 8; ++g) *(uint4*)(dst + g * 16) = make_uint4(0, 0, 0, 0);
        }
    }
    __syncthreads();

    // ---- HMMA mainloop: warp = 16 rows x 64 cols, single fp16 term ----
    int m0 = wid * 16;
    uint32_t aAh = s2u(smem + SM_AH) + (m0 + (lane & 15)) * ASTRIDE + ((lane >> 4) * 8) * 2;
    int bn   = (lane & 7) + ((lane >> 4) & 1) * 8;
    int bk16 = ((lane >> 3) & 1) * 16;
    uint32_t aBh = s2u(smem + SM_WH) + bn * ASTRIDE + bk16;

    float acc[8][4];
    #pragma unroll
    for (int nt = 0; nt < 8; ++nt)
        #pragma unroll
        for (int j = 0; j < 4; ++j) acc[nt][j] = 0.f;

    #pragma unroll
    for (int kk = 0; kk < 8; ++kk) {
        uint32_t ah[4];
        ldsm4(ah, aAh + kk * 32);
        #pragma unroll
        for (int n2 = 0; n2 < 4; ++n2) {
            uint32_t bh[4];
            ldsm4(bh, aBh + n2 * (16 * ASTRIDE) + kk * 32);
            mma_f16(acc[2*n2],     ah, bh);
            mma_f16(acc[2*n2 + 1], ah, bh + 2);
        }
    }

    // ---- epilogue in-fragment: bias + LReLU + row-norm; write fp16 ego_out ----
    const float* bs = (const float*)(smem + SM_BS);
    int q  = lane & 3;
    int gr = lane >> 2;
    float ss0 = 0.f, ss1 = 0.f;
    #pragma unroll
    for (int nt = 0; nt < 8; ++nt) {
        float b0 = bs[nt * 8 + 2 * q], b1 = bs[nt * 8 + 2 * q + 1];
        float c0 = acc[nt][0] + b0, c1 = acc[nt][1] + b1;
        float c2 = acc[nt][2] + b0, c3 = acc[nt][3] + b1;
        c0 = c0 > 0.f ? c0 : 0.2f * c0;
        c1 = c1 > 0.f ? c1 : 0.2f * c1;
        c2 = c2 > 0.f ? c2 : 0.2f * c2;
        c3 = c3 > 0.f ? c3 : 0.2f * c3;
        ss0 += c0 * c0 + c1 * c1;
        ss1 += c2 * c2 + c3 * c3;
        acc[nt][0] = c0; acc[nt][1] = c1; acc[nt][2] = c2; acc[nt][3] = c3;
    }
    ss0 += __shfl_xor_sync(0xffffffffu, ss0, 1);
    ss0 += __shfl_xor_sync(0xffffffffu, ss0, 2);
    ss1 += __shfl_xor_sync(0xffffffffu, ss1, 1);
    ss1 += __shfl_xor_sync(0xffffffffu, ss1, 2);
    float sc0 = 1.0f / fmaxf(sqrtf(ss0), 1e-12f);
    float sc1 = 1.0f / fmaxf(sqrtf(ss1), 1e-12f);

    int n0 = base + m0 + gr;
    int n1 = n0 + 8;
    #pragma unroll
    for (int nt = 0; nt < 8; ++nt) {
        int cw = nt * 4 + q;                 // half2 word index (cols 2cw, 2cw+1)
        if (n0 < N_NODES)
            ego_out[(size_t)n0 * 32 + cw] = pack_h2(acc[nt][0] * sc0, acc[nt][1] * sc0);
        if (n1 < N_NODES)
            ego_out[(size_t)n1 * 32 + cw] = pack_h2(acc[nt][2] * sc1, acc[nt][3] * sc1);
    }
}

// ---------------- output: dot(sum_k ego_k[u], sum_k ego_k[i]) / 16 ------------
__global__ __launch_bounds__(256) void out_kernel(const int* __restrict__ users,
                                                  const int* __restrict__ items,
                                                  float* __restrict__ out) {
    int b = blockIdx.x * 8 + (threadIdx.x >> 5);
    int lane = threadIdx.x & 31;
    if (b >= BATCH) return;
    size_t u = (size_t)__ldg(users + b) * 32 + lane;
    size_t i = ((size_t)N_USERS + __ldg(items + b)) * 32 + lane;
    float2 u0 = unpack_h2(g_ego0[u]), u1 = unpack_h2(g_ego1[u]);
    float2 u2 = unpack_h2(g_ego2[u]), u3 = unpack_h2(g_ego3[u]);
    float2 i0 = unpack_h2(g_ego0[i]), i1 = unpack_h2(g_ego1[i]);
    float2 i2 = unpack_h2(g_ego2[i]), i3 = unpack_h2(g_ego3[i]);
    float ux = u0.x + u1.x + u2.x + u3.x;
    float uy = u0.y + u1.y + u2.y + u3.y;
    float ix = i0.x + i1.x + i2.x + i3.x;
    float iy = i0.y + i1.y + i2.y + i3.y;
    float s = ux * ix + uy * iy;
    #pragma unroll
    for (int o = 16; o > 0; o >>= 1) s += __shfl_xor_sync(0xffffffffu, s, o);
    if (lane == 0) out[b] = s * (1.0f / 16.0f);
}

// ---------------- host launcher ------------------------------------------------
extern "C" void kernel_launch(void* const* d_in, const int* in_sizes, int n_in,
                              void* d_out, int out_size) {
    const int*   users    = (const int*)  d_in[0];
    const int*   items    = (const int*)  d_in[1];
    const int*   rows     = (const int*)  d_in[2];
    const int*   cols     = (const int*)  d_in[3];
    const float* vals     = (const float*)d_in[4];
    const float* user_emb = (const float*)d_in[5];
    const float* item_emb = (const float*)d_in[6];
    const float* W_gc     = (const float*)d_in[7];
    const float* b_gc     = (const float*)d_in[8];
    const float* W_bi     = (const float*)d_in[9];
    const float* b_bi     = (const float*)d_in[10];
    float*       out      = (float*)d_out;

    cudaFuncSetAttribute(transform_kernel,
                         cudaFuncAttributeMaxDynamicSharedMemorySize, SMEM_TR);

    uint32_t* ego[4];
    cudaGetSymbolAddress((void**)&ego[0], g_ego0);
    cudaGetSymbolAddress((void**)&ego[1], g_ego1);
    cudaGetSymbolAddress((void**)&ego[2], g_ego2);
    cudaGetSymbolAddress((void**)&ego[3], g_ego3);
    unsigned char* wt = nullptr;  float* bsum = nullptr;
    cudaGetSymbolAddress((void**)&wt, g_wt);
    cudaGetSymbolAddress((void**)&bsum, g_bsum);

    const int egrid = (N_EDGES + 255) / 256;
    const int ngrid = (N_NODES + 255) / 256;

    init_kernel<<<(N_NODES * 8 + 255) / 256, 256>>>((const float4*)user_emb,
                                                    (const float4*)item_emb);
    prep_w_kernel<<<3, 256>>>(W_gc, b_gc, W_bi, b_bi);
    hist_kernel<<<egrid, 256>>>(rows);
    offset_kernel<<<ngrid, 256>>>();
    scatter_kernel<<<egrid, 256>>>(rows, cols, vals);

    const int lgrid = (N_NODES + TTILE - 1) / TTILE;
    const int sgrid = (N_NODES + 7) / 8;
    for (int k = 0; k < 3; ++k) {
        spmm_csr_kernel<<<sgrid, 256>>>(ego[k]);
        transform_kernel<<<lgrid, 256, SMEM_TR>>>(ego[k], ego[k + 1],
            wt + (size_t)k * WT_BYTES, bsum + k * 64);
    }

    out_kernel<<<BATCH / 8, 256>>>(users, items, out);
}

// round 16
// speedup vs baseline: 1.5135x; 1.0763x over previous
#include <cuda_runtime.h>
#include <cuda_fp16.h>
#include <cstdint>

#define N_USERS 100000
#define M_ITEMS 200000
#define N_NODES 300000
#define N_EDGES 1200000
#define BATCH   4096

#define TTILE   128
#define ASTRIDE 272                         // bytes per A/W row (136 fp16, pad)
#define WT_BYTES (64 * ASTRIDE)             // single-fp16 W tile, 17408 B

// ---------------- scratch (device globals: allocation-free rule) -------------
// ego/side stored as packed half2 (uint32 per 2 features), 32 words/node
__device__ uint32_t g_ego0[N_NODES * 32];
__device__ uint32_t g_ego1[N_NODES * 32];
__device__ uint32_t g_ego2[N_NODES * 32];
__device__ uint32_t g_ego3[N_NODES * 32];
__device__ uint32_t g_sideh[N_NODES * 32];
__device__ int    g_deg [N_NODES];
__device__ int    g_ptr [N_NODES];
__device__ int    g_fill[N_NODES];
__device__ int    g_cursor;
__device__ int    g_ccol[N_EDGES];
__device__ float  g_cval[N_EDGES];
__device__ __align__(16) unsigned char g_wt[3][WT_BYTES];
__device__ float  g_bsum[3][64];

// ---------------- helpers ------------------------------------------------------
__device__ __forceinline__ uint32_t s2u(const void* p) {
    return (uint32_t)__cvta_generic_to_shared(p);
}
__device__ __forceinline__ void ldsm4(uint32_t* r, uint32_t a) {
    asm volatile("ldmatrix.sync.aligned.m8n8.x4.shared.b16 {%0,%1,%2,%3}, [%4];"
                 : "=r"(r[0]), "=r"(r[1]), "=r"(r[2]), "=r"(r[3]) : "r"(a));
}
__device__ __forceinline__ void mma_f16(float* c, const uint32_t* a, const uint32_t* b) {
    asm volatile("mma.sync.aligned.m16n8k16.row.col.f32.f16.f16.f32 "
                 "{%0,%1,%2,%3}, {%4,%5,%6,%7}, {%8,%9}, {%0,%1,%2,%3};"
                 : "+f"(c[0]), "+f"(c[1]), "+f"(c[2]), "+f"(c[3])
                 : "r"(a[0]), "r"(a[1]), "r"(a[2]), "r"(a[3]), "r"(b[0]), "r"(b[1]));
}
__device__ __forceinline__ uint32_t pack_h2(float a, float b) {
    __half2 h = __floats2half2_rn(a, b);
    return *reinterpret_cast<uint32_t*>(&h);
}
__device__ __forceinline__ float2 unpack_h2(uint32_t w) {
    return __half22float2(*reinterpret_cast<__half2*>(&w));
}
__device__ __forceinline__ uint32_t hmul2u(uint32_t a, uint32_t b) {
    __half2 r = __hmul2(*reinterpret_cast<__half2*>(&a), *reinterpret_cast<__half2*>(&b));
    return *reinterpret_cast<uint32_t*>(&r);
}

// ---------------- init: ego0 = fp16(concat(user,item)); CSR counters = 0 -------
__global__ __launch_bounds__(256) void init_kernel(const float4* __restrict__ ue,
                                                   const float4* __restrict__ ie) {
    int i = blockIdx.x * 256 + threadIdx.x;   // one uint4 (8 halfs = 8 floats)
    if (i < N_NODES) { g_deg[i] = 0; g_fill[i] = 0; }
    if (i == 0) g_cursor = 0;
    if (i >= N_NODES * 8) return;
    int node = i >> 3;
    int q    = i & 7;
    const float4* src = (node < N_USERS) ? (ue + (size_t)node * 16 + q * 2)
                                         : (ie + (size_t)(node - N_USERS) * 16 + q * 2);
    float4 v0 = __ldg(src);
    float4 v1 = __ldg(src + 1);
    ((uint4*)g_ego0)[i] = make_uint4(pack_h2(v0.x, v0.y), pack_h2(v0.z, v0.w),
                                     pack_h2(v1.x, v1.y), pack_h2(v1.z, v1.w));
}

// ---------------- one-time W fp16 tile + bias sums ------------------------------
__global__ __launch_bounds__(256) void prep_w_kernel(const float* __restrict__ W_gc,
                                                     const float* __restrict__ b_gc,
                                                     const float* __restrict__ W_bi,
                                                     const float* __restrict__ b_bi) {
    int layer = blockIdx.x;
    const float* Wgc = W_gc + layer * 4096;
    const float* Wbi = W_bi + layer * 4096;
    int tid = threadIdx.x;
    if (tid < 64) g_bsum[layer][tid] = b_gc[layer * 64 + tid] + b_bi[layer * 64 + tid];
    int n  = tid & 63;
    int ks = (tid >> 6) * 32;
    unsigned char* wh = g_wt[layer] + n * ASTRIDE + ks * 2;
    #pragma unroll
    for (int g = 0; g < 4; ++g) {
        uint32_t hv[4];
        #pragma unroll
        for (int p = 0; p < 4; ++p) {
            int k = ks + g * 8 + 2 * p;
            float v0 = (k < 64)     ? __ldg(Wgc + (size_t)k * 64 + n)
                                    : __ldg(Wbi + (size_t)(k - 64) * 64 + n);
            float v1 = (k + 1 < 64) ? __ldg(Wgc + (size_t)(k + 1) * 64 + n)
                                    : __ldg(Wbi + (size_t)(k + 1 - 64) * 64 + n);
            hv[p] = pack_h2(v0, v1);
        }
        *(uint4*)(wh + g * 16) = make_uint4(hv[0], hv[1], hv[2], hv[3]);
    }
}

// ---------------- CSR build ------------------------------------------------------
__global__ __launch_bounds__(256) void hist_kernel(const int* __restrict__ rows) {
    int e = blockIdx.x * 256 + threadIdx.x;
    if (e < N_EDGES) atomicAdd(&g_deg[__ldg(rows + e)], 1);
}

__global__ __launch_bounds__(256) void offset_kernel() {
    int i = blockIdx.x * 256 + threadIdx.x;
    int lane = threadIdx.x & 31;
    int d = (i < N_NODES) ? g_deg[i] : 0;
    int s = d;
    #pragma unroll
    for (int o = 1; o < 32; o <<= 1) {
        int t = __shfl_up_sync(0xffffffffu, s, o);
        if (lane >= o) s += t;
    }
    int total = __shfl_sync(0xffffffffu, s, 31);
    int base = 0;
    if (lane == 31) base = atomicAdd(&g_cursor, total);
    base = __shfl_sync(0xffffffffu, base, 31);
    if (i < N_NODES) g_ptr[i] = base + s - d;
}

__global__ __launch_bounds__(256) void scatter_kernel(const int*   __restrict__ rows,
                                                      const int*   __restrict__ cols,
                                                      const float* __restrict__ vals) {
    int e = blockIdx.x * 256 + threadIdx.x;
    if (e >= N_EDGES) return;
    int r = __ldg(rows + e);
    int pos = g_ptr[r] + atomicAdd(&g_fill[r], 1);
    g_ccol[pos] = __ldg(cols + e);
    g_cval[pos] = __ldg(vals + e);
}

// ---------------- spmm (CSR, 2 rows/warp, fp16 gather, fp32 accum) --------------
// lanes 0-15 -> row A, 16-31 -> row B; lane owns 4 features (one uint2).
__global__ __launch_bounds__(256) void spmm_csr_kernel(const uint32_t* __restrict__ ego_in) {
    int row = blockIdx.x * 16 + (threadIdx.x >> 4);
    int sl  = threadIdx.x & 15;
    if (row >= N_NODES) return;
    int p = __ldg(&g_ptr[row]);
    int d = __ldg(&g_deg[row]);
    const uint2* ego2 = (const uint2*)ego_in;

    float4 a0 = make_float4(0.f, 0.f, 0.f, 0.f);
    float4 a1 = make_float4(0.f, 0.f, 0.f, 0.f);
    int j = 0;
    for (; j + 4 <= d; j += 4) {
        int   c0 = __ldg(&g_ccol[p + j]);
        int   c1 = __ldg(&g_ccol[p + j + 1]);
        int   c2 = __ldg(&g_ccol[p + j + 2]);
        int   c3 = __ldg(&g_ccol[p + j + 3]);
        float v0 = __ldg(&g_cval[p + j]);
        float v1 = __ldg(&g_cval[p + j + 1]);
        float v2 = __ldg(&g_cval[p + j + 2]);
        float v3 = __ldg(&g_cval[p + j + 3]);
        uint2 w0 = __ldg(ego2 + (size_t)c0 * 16 + sl);
        uint2 w1 = __ldg(ego2 + (size_t)c1 * 16 + sl);
        uint2 w2 = __ldg(ego2 + (size_t)c2 * 16 + sl);
        uint2 w3 = __ldg(ego2 + (size_t)c3 * 16 + sl);
        float2 x0a = unpack_h2(w0.x), x0b = unpack_h2(w0.y);
        float2 x1a = unpack_h2(w1.x), x1b = unpack_h2(w1.y);
        float2 x2a = unpack_h2(w2.x), x2b = unpack_h2(w2.y);
        float2 x3a = unpack_h2(w3.x), x3b = unpack_h2(w3.y);
        a0.x += v0 * x0a.x; a0.y += v0 * x0a.y; a0.z += v0 * x0b.x; a0.w += v0 * x0b.y;
        a1.x += v1 * x1a.x; a1.y += v1 * x1a.y; a1.z += v1 * x1b.x; a1.w += v1 * x1b.y;
        a0.x += v2 * x2a.x; a0.y += v2 * x2a.y; a0.z += v2 * x2b.x; a0.w += v2 * x2b.y;
        a1.x += v3 * x3a.x; a1.y += v3 * x3a.y; a1.z += v3 * x3b.x; a1.w += v3 * x3b.y;
    }
    if (j < d) {
        int   c = __ldg(&g_ccol[p + j]);
        float v = __ldg(&g_cval[p + j]);
        for (++j; j <= d; ++j) {
            int   cn = 0; float vn = 0.f;
            if (j < d) { cn = __ldg(&g_ccol[p + j]); vn = __ldg(&g_cval[p + j]); }
            uint2 w = __ldg(ego2 + (size_t)c * 16 + sl);
            float2 xa = unpack_h2(w.x), xb = unpack_h2(w.y);
            a0.x += v * xa.x; a0.y += v * xa.y; a0.z += v * xb.x; a0.w += v * xb.y;
            c = cn; v = vn;
        }
    }
    a0.x += a1.x; a0.y += a1.y; a0.z += a1.z; a0.w += a1.w;
    ((uint2*)g_sideh)[(size_t)row * 16 + sl] =
        make_uint2(pack_h2(a0.x, a0.y), pack_h2(a0.z, a0.w));
}

// ---------------- transform via mma.sync fp16 GEMM (single term) ----------------
// A (fp16) = [S | E*S]; B (fp16) = [Wgc; Wbi]^T. smem 52.5KB -> 4 CTAs/SM.
#define SM_BS   0
#define SM_AH   256
#define SM_WH   (SM_AH + 128 * ASTRIDE)     // 35072
#define SMEM_TR (SM_WH + WT_BYTES)          // 52480

__global__ __launch_bounds__(256) void transform_kernel(const uint32_t* __restrict__ ego_in,
                                                        uint32_t*       __restrict__ ego_out,
                                                        const unsigned char* __restrict__ wt,
                                                        const float*  __restrict__ bsum) {
    extern __shared__ unsigned char smem[];
    int tid  = threadIdx.x;
    int wid  = tid >> 5;
    int lane = tid & 31;
    int base = blockIdx.x * TTILE;

    // ---- bias sum (precomputed) ----
    if (tid < 64) ((float*)(smem + SM_BS))[tid] = __ldg(bsum + tid);

    // ---- stage W tile: contiguous uint4 copy ----
    {
        const uint4* src = (const uint4*)wt;
        uint4* dst = (uint4*)(smem + SM_WH);
        #pragma unroll
        for (int i = tid; i < WT_BYTES / 16; i += 256) dst[i] = __ldg(src + i);
    }

    // ---- stage A: thread = (row, half). half0: copy S; half1: E*S (hmul2) ----
    {
        int row  = tid >> 1;
        int half = tid & 1;
        int n    = base + row;
        unsigned char* dst = smem + SM_AH + row * ASTRIDE + half * 128;
        if (n < N_NODES) {
            const uint4* sp = (const uint4*)(g_sideh + (size_t)n * 32);
            if (half == 0) {
                #pragma unroll
                for (int g = 0; g < 8; ++g) *(uint4*)(dst + g * 16) = __ldg(sp + g);
            } else {
                const uint4* ep = (const uint4*)(ego_in + (size_t)n * 32);
                #pragma unroll
                for (int g = 0; g < 8; ++g) {
                    uint4 s = __ldg(sp + g);
                    uint4 e = __ldg(ep + g);
                    *(uint4*)(dst + g * 16) = make_uint4(hmul2u(s.x, e.x), hmul2u(s.y, e.y),
                                                         hmul2u(s.z, e.z), hmul2u(s.w, e.w));
                }
            }
        } else {
            #pragma unroll
            for (int g = 0; g < 8; ++g) *(uint4*)(dst + g * 16) = make_uint4(0, 0, 0, 0);
        }
    }
    __syncthreads();

    // ---- HMMA mainloop: warp = 16 rows x 64 cols, single fp16 term ----
    int m0 = wid * 16;
    uint32_t aAh = s2u(smem + SM_AH) + (m0 + (lane & 15)) * ASTRIDE + ((lane >> 4) * 8) * 2;
    int bn   = (lane & 7) + ((lane >> 4) & 1) * 8;
    int bk16 = ((lane >> 3) & 1) * 16;
    uint32_t aBh = s2u(smem + SM_WH) + bn * ASTRIDE + bk16;

    float acc[8][4];
    #pragma unroll
    for (int nt = 0; nt < 8; ++nt)
        #pragma unroll
        for (int j = 0; j < 4; ++j) acc[nt][j] = 0.f;

    #pragma unroll
    for (int kk = 0; kk < 8; ++kk) {
        uint32_t ah[4];
        ldsm4(ah, aAh + kk * 32);
        #pragma unroll
        for (int n2 = 0; n2 < 4; ++n2) {
            uint32_t bh[4];
            ldsm4(bh, aBh + n2 * (16 * ASTRIDE) + kk * 32);
            mma_f16(acc[2*n2],     ah, bh);
            mma_f16(acc[2*n2 + 1], ah, bh + 2);
        }
    }

    // ---- epilogue in-fragment: bias + LReLU + row-norm; write fp16 ego_out ----
    const float* bs = (const float*)(smem + SM_BS);
    int q  = lane & 3;
    int gr = lane >> 2;
    float ss0 = 0.f, ss1 = 0.f;
    #pragma unroll
    for (int nt = 0; nt < 8; ++nt) {
        float b0 = bs[nt * 8 + 2 * q], b1 = bs[nt * 8 + 2 * q + 1];
        float c0 = acc[nt][0] + b0, c1 = acc[nt][1] + b1;
        float c2 = acc[nt][2] + b0, c3 = acc[nt][3] + b1;
        c0 = c0 > 0.f ? c0 : 0.2f * c0;
        c1 = c1 > 0.f ? c1 : 0.2f * c1;
        c2 = c2 > 0.f ? c2 : 0.2f * c2;
        c3 = c3 > 0.f ? c3 : 0.2f * c3;
        ss0 += c0 * c0 + c1 * c1;
        ss1 += c2 * c2 + c3 * c3;
        acc[nt][0] = c0; acc[nt][1] = c1; acc[nt][2] = c2; acc[nt][3] = c3;
    }
    ss0 += __shfl_xor_sync(0xffffffffu, ss0, 1);
    ss0 += __shfl_xor_sync(0xffffffffu, ss0, 2);
    ss1 += __shfl_xor_sync(0xffffffffu, ss1, 1);
    ss1 += __shfl_xor_sync(0xffffffffu, ss1, 2);
    float sc0 = 1.0f / fmaxf(sqrtf(ss0), 1e-12f);
    float sc1 = 1.0f / fmaxf(sqrtf(ss1), 1e-12f);

    int n0 = base + m0 + gr;
    int n1 = n0 + 8;
    #pragma unroll
    for (int nt = 0; nt < 8; ++nt) {
        int cw = nt * 4 + q;                 // half2 word index (cols 2cw, 2cw+1)
        if (n0 < N_NODES)
            ego_out[(size_t)n0 * 32 + cw] = pack_h2(acc[nt][0] * sc0, acc[nt][1] * sc0);
        if (n1 < N_NODES)
            ego_out[(size_t)n1 * 32 + cw] = pack_h2(acc[nt][2] * sc1, acc[nt][3] * sc1);
    }
}

// ---------------- output: dot(sum_k ego_k[u], sum_k ego_k[i]) / 16 ------------
__global__ __launch_bounds__(256) void out_kernel(const int* __restrict__ users,
                                                  const int* __restrict__ items,
                                                  float* __restrict__ out) {
    int b = blockIdx.x * 8 + (threadIdx.x >> 5);
    int lane = threadIdx.x & 31;
    if (b >= BATCH) return;
    size_t u = (size_t)__ldg(users + b) * 32 + lane;
    size_t i = ((size_t)N_USERS + __ldg(items + b)) * 32 + lane;
    float2 u0 = unpack_h2(g_ego0[u]), u1 = unpack_h2(g_ego1[u]);
    float2 u2 = unpack_h2(g_ego2[u]), u3 = unpack_h2(g_ego3[u]);
    float2 i0 = unpack_h2(g_ego0[i]), i1 = unpack_h2(g_ego1[i]);
    float2 i2 = unpack_h2(g_ego2[i]), i3 = unpack_h2(g_ego3[i]);
    float ux = u0.x + u1.x + u2.x + u3.x;
    float uy = u0.y + u1.y + u2.y + u3.y;
    float ix = i0.x + i1.x + i2.x + i3.x;
    float iy = i0.y + i1.y + i2.y + i3.y;
    float s = ux * ix + uy * iy;
    #pragma unroll
    for (int o = 16; o > 0; o >>= 1) s += __shfl_xor_sync(0xffffffffu, s, o);
    if (lane == 0) out[b] = s * (1.0f / 16.0f);
}

// ---------------- host launcher ------------------------------------------------
extern "C" void kernel_launch(void* const* d_in, const int* in_sizes, int n_in,
                              void* d_out, int out_size) {
    const int*   users    = (const int*)  d_in[0];
    const int*   items    = (const int*)  d_in[1];
    const int*   rows     = (const int*)  d_in[2];
    const int*   cols     = (const int*)  d_in[3];
    const float* vals     = (const float*)d_in[4];
    const float* user_emb = (const float*)d_in[5];
    const float* item_emb = (const float*)d_in[6];
    const float* W_gc     = (const float*)d_in[7];
    const float* b_gc     = (const float*)d_in[8];
    const float* W_bi     = (const float*)d_in[9];
    const float* b_bi     = (const float*)d_in[10];
    float*       out      = (float*)d_out;

    cudaFuncSetAttribute(transform_kernel,
                         cudaFuncAttributeMaxDynamicSharedMemorySize, SMEM_TR);

    uint32_t* ego[4];
    cudaGetSymbolAddress((void**)&ego[0], g_ego0);
    cudaGetSymbolAddress((void**)&ego[1], g_ego1);
    cudaGetSymbolAddress((void**)&ego[2], g_ego2);
    cudaGetSymbolAddress((void**)&ego[3], g_ego3);
    unsigned char* wt = nullptr;  float* bsum = nullptr;
    cudaGetSymbolAddress((void**)&wt, g_wt);
    cudaGetSymbolAddress((void**)&bsum, g_bsum);

    const int egrid = (N_EDGES + 255) / 256;
    const int ngrid = (N_NODES + 255) / 256;

    init_kernel<<<(N_NODES * 8 + 255) / 256, 256>>>((const float4*)user_emb,
                                                    (const float4*)item_emb);
    prep_w_kernel<<<3, 256>>>(W_gc, b_gc, W_bi, b_bi);
    hist_kernel<<<egrid, 256>>>(rows);
    offset_kernel<<<ngrid, 256>>>();
    scatter_kernel<<<egrid, 256>>>(rows, cols, vals);

    const int lgrid = (N_NODES + TTILE - 1) / TTILE;
    const int sgrid = (N_NODES + 15) / 16;
    for (int k = 0; k < 3; ++k) {
        spmm_csr_kernel<<<sgrid, 256>>>(ego[k]);
        transform_kernel<<<lgrid, 256, SMEM_TR>>>(ego[k], ego[k + 1],
            wt + (size_t)k * WT_BYTES, bsum + k * 64);
    }

    out_kernel<<<BATCH / 8, 256>>>(users, items, out);
}

// round 17
// speedup vs baseline: 1.7246x; 1.1395x over previous
#include <cuda_runtime.h>
#include <cuda_fp16.h>
#include <cstdint>

#define N_USERS 100000
#define M_ITEMS 200000
#define N_NODES 300000
#define N_EDGES 1200000
#define BATCH   4096

#define TTILE   128
#define ASTRIDE 272                         // bytes per A/W row (136 fp16, pad)
#define WT_BYTES (64 * ASTRIDE)             // single-fp16 W tile, 17408 B

// ---------------- scratch (device globals: allocation-free rule) -------------
// ego/side stored as packed half2 (uint32 per 2 features), 32 words/node
__device__ uint32_t g_ego0[N_NODES * 32];
__device__ uint32_t g_ego1[N_NODES * 32];
__device__ uint32_t g_ego2[N_NODES * 32];
__device__ uint32_t g_ego3[N_NODES * 32];
__device__ uint32_t g_sideh[N_NODES * 32];
__device__ int    g_deg [N_NODES];
__device__ int    g_ptr [N_NODES];
__device__ int    g_fill[N_NODES];
__device__ int    g_cursor;
__device__ int    g_ccol[N_EDGES];
__device__ float  g_cval[N_EDGES];
__device__ __align__(16) unsigned char g_wt[3][WT_BYTES];
__device__ float  g_bsum[3][64];

// ---------------- helpers ------------------------------------------------------
__device__ __forceinline__ uint32_t s2u(const void* p) {
    return (uint32_t)__cvta_generic_to_shared(p);
}
__device__ __forceinline__ void ldsm4(uint32_t* r, uint32_t a) {
    asm volatile("ldmatrix.sync.aligned.m8n8.x4.shared.b16 {%0,%1,%2,%3}, [%4];"
                 : "=r"(r[0]), "=r"(r[1]), "=r"(r[2]), "=r"(r[3]) : "r"(a));
}
__device__ __forceinline__ void mma_f16(float* c, const uint32_t* a, const uint32_t* b) {
    asm volatile("mma.sync.aligned.m16n8k16.row.col.f32.f16.f16.f32 "
                 "{%0,%1,%2,%3}, {%4,%5,%6,%7}, {%8,%9}, {%0,%1,%2,%3};"
                 : "+f"(c[0]), "+f"(c[1]), "+f"(c[2]), "+f"(c[3])
                 : "r"(a[0]), "r"(a[1]), "r"(a[2]), "r"(a[3]), "r"(b[0]), "r"(b[1]));
}
__device__ __forceinline__ uint32_t pack_h2(float a, float b) {
    __half2 h = __floats2half2_rn(a, b);
    return *reinterpret_cast<uint32_t*>(&h);
}
__device__ __forceinline__ float2 unpack_h2(uint32_t w) {
    return __half22float2(*reinterpret_cast<__half2*>(&w));
}
__device__ __forceinline__ uint32_t hmul2u(uint32_t a, uint32_t b) {
    __half2 r = __hmul2(*reinterpret_cast<__half2*>(&a), *reinterpret_cast<__half2*>(&b));
    return *reinterpret_cast<uint32_t*>(&r);
}

// ---------------- init: ego0 = fp16(concat(user,item)); CSR counters = 0 -------
__global__ __launch_bounds__(256) void init_kernel(const float4* __restrict__ ue,
                                                   const float4* __restrict__ ie) {
    int i = blockIdx.x * 256 + threadIdx.x;   // one uint4 (8 halfs = 8 floats)
    if (i < N_NODES) { g_deg[i] = 0; g_fill[i] = 0; }
    if (i == 0) g_cursor = 0;
    if (i >= N_NODES * 8) return;
    int node = i >> 3;
    int q    = i & 7;
    const float4* src = (node < N_USERS) ? (ue + (size_t)node * 16 + q * 2)
                                         : (ie + (size_t)(node - N_USERS) * 16 + q * 2);
    float4 v0 = __ldg(src);
    float4 v1 = __ldg(src + 1);
    ((uint4*)g_ego0)[i] = make_uint4(pack_h2(v0.x, v0.y), pack_h2(v0.z, v0.w),
                                     pack_h2(v1.x, v1.y), pack_h2(v1.z, v1.w));
}

// ---------------- one-time W fp16 tile + bias sums ------------------------------
__global__ __launch_bounds__(256) void prep_w_kernel(const float* __restrict__ W_gc,
                                                     const float* __restrict__ b_gc,
                                                     const float* __restrict__ W_bi,
                                                     const float* __restrict__ b_bi) {
    int layer = blockIdx.x;
    const float* Wgc = W_gc + layer * 4096;
    const float* Wbi = W_bi + layer * 4096;
    int tid = threadIdx.x;
    if (tid < 64) g_bsum[layer][tid] = b_gc[layer * 64 + tid] + b_bi[layer * 64 + tid];
    int n  = tid & 63;
    int ks = (tid >> 6) * 32;
    unsigned char* wh = g_wt[layer] + n * ASTRIDE + ks * 2;
    #pragma unroll
    for (int g = 0; g < 4; ++g) {
        uint32_t hv[4];
        #pragma unroll
        for (int p = 0; p < 4; ++p) {
            int k = ks + g * 8 + 2 * p;
            float v0 = (k < 64)     ? __ldg(Wgc + (size_t)k * 64 + n)
                                    : __ldg(Wbi + (size_t)(k - 64) * 64 + n);
            float v1 = (k + 1 < 64) ? __ldg(Wgc + (size_t)(k + 1) * 64 + n)
                                    : __ldg(Wbi + (size_t)(k + 1 - 64) * 64 + n);
            hv[p] = pack_h2(v0, v1);
        }
        *(uint4*)(wh + g * 16) = make_uint4(hv[0], hv[1], hv[2], hv[3]);
    }
}

// ---------------- CSR build ------------------------------------------------------
__global__ __launch_bounds__(256) void hist_kernel(const int* __restrict__ rows) {
    int e = blockIdx.x * 256 + threadIdx.x;
    if (e < N_EDGES) atomicAdd(&g_deg[__ldg(rows + e)], 1);
}

__global__ __launch_bounds__(256) void offset_kernel() {
    int i = blockIdx.x * 256 + threadIdx.x;
    int lane = threadIdx.x & 31;
    int d = (i < N_NODES) ? g_deg[i] : 0;
    int s = d;
    #pragma unroll
    for (int o = 1; o < 32; o <<= 1) {
        int t = __shfl_up_sync(0xffffffffu, s, o);
        if (lane >= o) s += t;
    }
    int total = __shfl_sync(0xffffffffu, s, 31);
    int base = 0;
    if (lane == 31) base = atomicAdd(&g_cursor, total);
    base = __shfl_sync(0xffffffffu, base, 31);
    if (i < N_NODES) g_ptr[i] = base + s - d;
}

__global__ __launch_bounds__(256) void scatter_kernel(const int*   __restrict__ rows,
                                                      const int*   __restrict__ cols,
                                                      const float* __restrict__ vals) {
    int e = blockIdx.x * 256 + threadIdx.x;
    if (e >= N_EDGES) return;
    int r = __ldg(rows + e);
    int pos = g_ptr[r] + atomicAdd(&g_fill[r], 1);
    g_ccol[pos] = __ldg(cols + e);
    g_cval[pos] = __ldg(vals + e);
}

// ---------------- spmm (CSR, 4 rows/warp, fp16 gather, fp32 accum) --------------
// 8 lanes per row; lane owns 8 features (one uint4 = 16 B); row line = 128 B.
__global__ __launch_bounds__(256) void spmm_csr_kernel(const uint32_t* __restrict__ ego_in) {
    int row = blockIdx.x * 32 + (threadIdx.x >> 3);
    int sl  = threadIdx.x & 7;
    if (row >= N_NODES) return;
    int p = __ldg(&g_ptr[row]);
    int d = __ldg(&g_deg[row]);
    const uint4* ego4 = (const uint4*)ego_in;

    float a0[8] = {0.f, 0.f, 0.f, 0.f, 0.f, 0.f, 0.f, 0.f};
    float a1[8] = {0.f, 0.f, 0.f, 0.f, 0.f, 0.f, 0.f, 0.f};
    int j = 0;
    for (; j + 4 <= d; j += 4) {
        int   c0 = __ldg(&g_ccol[p + j]);
        int   c1 = __ldg(&g_ccol[p + j + 1]);
        int   c2 = __ldg(&g_ccol[p + j + 2]);
        int   c3 = __ldg(&g_ccol[p + j + 3]);
        float v0 = __ldg(&g_cval[p + j]);
        float v1 = __ldg(&g_cval[p + j + 1]);
        float v2 = __ldg(&g_cval[p + j + 2]);
        float v3 = __ldg(&g_cval[p + j + 3]);
        uint4 w0 = __ldg(ego4 + (size_t)c0 * 8 + sl);
        uint4 w1 = __ldg(ego4 + (size_t)c1 * 8 + sl);
        uint4 w2 = __ldg(ego4 + (size_t)c2 * 8 + sl);
        uint4 w3 = __ldg(ego4 + (size_t)c3 * 8 + sl);
        {
            float2 xa = unpack_h2(w0.x), xb = unpack_h2(w0.y);
            float2 xc = unpack_h2(w0.z), xd = unpack_h2(w0.w);
            a0[0] += v0 * xa.x; a0[1] += v0 * xa.y; a0[2] += v0 * xb.x; a0[3] += v0 * xb.y;
            a0[4] += v0 * xc.x; a0[5] += v0 * xc.y; a0[6] += v0 * xd.x; a0[7] += v0 * xd.y;
        }
        {
            float2 xa = unpack_h2(w1.x), xb = unpack_h2(w1.y);
            float2 xc = unpack_h2(w1.z), xd = unpack_h2(w1.w);
            a1[0] += v1 * xa.x; a1[1] += v1 * xa.y; a1[2] += v1 * xb.x; a1[3] += v1 * xb.y;
            a1[4] += v1 * xc.x; a1[5] += v1 * xc.y; a1[6] += v1 * xd.x; a1[7] += v1 * xd.y;
        }
        {
            float2 xa = unpack_h2(w2.x), xb = unpack_h2(w2.y);
            float2 xc = unpack_h2(w2.z), xd = unpack_h2(w2.w);
            a0[0] += v2 * xa.x; a0[1] += v2 * xa.y; a0[2] += v2 * xb.x; a0[3] += v2 * xb.y;
            a0[4] += v2 * xc.x; a0[5] += v2 * xc.y; a0[6] += v2 * xd.x; a0[7] += v2 * xd.y;
        }
        {
            float2 xa = unpack_h2(w3.x), xb = unpack_h2(w3.y);
            float2 xc = unpack_h2(w3.z), xd = unpack_h2(w3.w);
            a1[0] += v3 * xa.x; a1[1] += v3 * xa.y; a1[2] += v3 * xb.x; a1[3] += v3 * xb.y;
            a1[4] += v3 * xc.x; a1[5] += v3 * xc.y; a1[6] += v3 * xd.x; a1[7] += v3 * xd.y;
        }
    }
    if (j < d) {
        int   c = __ldg(&g_ccol[p + j]);
        float v = __ldg(&g_cval[p + j]);
        for (++j; j <= d; ++j) {
            int   cn = 0; float vn = 0.f;
            if (j < d) { cn = __ldg(&g_ccol[p + j]); vn = __ldg(&g_cval[p + j]); }
            uint4 w = __ldg(ego4 + (size_t)c * 8 + sl);
            float2 xa = unpack_h2(w.x), xb = unpack_h2(w.y);
            float2 xc = unpack_h2(w.z), xd = unpack_h2(w.w);
            a0[0] += v * xa.x; a0[1] += v * xa.y; a0[2] += v * xb.x; a0[3] += v * xb.y;
            a0[4] += v * xc.x; a0[5] += v * xc.y; a0[6] += v * xd.x; a0[7] += v * xd.y;
            c = cn; v = vn;
        }
    }
    #pragma unroll
    for (int t = 0; t < 8; ++t) a0[t] += a1[t];
    ((uint4*)g_sideh)[(size_t)row * 8 + sl] =
        make_uint4(pack_h2(a0[0], a0[1]), pack_h2(a0[2], a0[3]),
                   pack_h2(a0[4], a0[5]), pack_h2(a0[6], a0[7]));
}

// ---------------- transform via mma.sync fp16 GEMM (single term) ----------------
// A (fp16) = [S | E*S]; B (fp16) = [Wgc; Wbi]^T. smem 52.5KB -> 4 CTAs/SM.
#define SM_BS   0
#define SM_AH   256
#define SM_WH   (SM_AH + 128 * ASTRIDE)     // 35072
#define SMEM_TR (SM_WH + WT_BYTES)          // 52480

__global__ __launch_bounds__(256) void transform_kernel(const uint32_t* __restrict__ ego_in,
                                                        uint32_t*       __restrict__ ego_out,
                                                        const unsigned char* __restrict__ wt,
                                                        const float*  __restrict__ bsum) {
    extern __shared__ unsigned char smem[];
    int tid  = threadIdx.x;
    int wid  = tid >> 5;
    int lane = tid & 31;
    int base = blockIdx.x * TTILE;

    // ---- bias sum (precomputed) ----
    if (tid < 64) ((float*)(smem + SM_BS))[tid] = __ldg(bsum + tid);

    // ---- stage W tile: contiguous uint4 copy ----
    {
        const uint4* src = (const uint4*)wt;
        uint4* dst = (uint4*)(smem + SM_WH);
        #pragma unroll
        for (int i = tid; i < WT_BYTES / 16; i += 256) dst[i] = __ldg(src + i);
    }

    // ---- stage A: thread = (row, feature-half). S read once; writes S+U tiles --
    {
        int row = tid >> 1;
        int fh  = tid & 1;                   // features 32*fh .. 32*fh+31
        int n   = base + row;
        unsigned char* dstS = smem + SM_AH + row * ASTRIDE + fh * 64;
        unsigned char* dstU = dstS + 128;
        if (n < N_NODES) {
            const uint4* sp = (const uint4*)(g_sideh + (size_t)n * 32) + fh * 4;
            const uint4* ep = (const uint4*)(ego_in  + (size_t)n * 32) + fh * 4;
            #pragma unroll
            for (int g = 0; g < 4; ++g) {
                uint4 s = __ldg(sp + g);
                uint4 e = __ldg(ep + g);
                *(uint4*)(dstS + g * 16) = s;
                *(uint4*)(dstU + g * 16) = make_uint4(hmul2u(s.x, e.x), hmul2u(s.y, e.y),
                                                      hmul2u(s.z, e.z), hmul2u(s.w, e.w));
            }
        } else {
            #pragma unroll
            for (int g = 0; g < 4; ++g) {
                *(uint4*)(dstS + g * 16) = make_uint4(0, 0, 0, 0);
                *(uint4*)(dstU + g * 16) = make_uint4(0, 0, 0, 0);
            }
        }
    }
    __syncthreads();

    // ---- HMMA mainloop: warp = 16 rows x 64 cols, single fp16 term ----
    int m0 = wid * 16;
    uint32_t aAh = s2u(smem + SM_AH) + (m0 + (lane & 15)) * ASTRIDE + ((lane >> 4) * 8) * 2;
    int bn   = (lane & 7) + ((lane >> 4) & 1) * 8;
    int bk16 = ((lane >> 3) & 1) * 16;
    uint32_t aBh = s2u(smem + SM_WH) + bn * ASTRIDE + bk16;

    float acc[8][4];
    #pragma unroll
    for (int nt = 0; nt < 8; ++nt)
        #pragma unroll
        for (int j = 0; j < 4; ++j) acc[nt][j] = 0.f;

    #pragma unroll
    for (int kk = 0; kk < 8; ++kk) {
        uint32_t ah[4];
        ldsm4(ah, aAh + kk * 32);
        #pragma unroll
        for (int n2 = 0; n2 < 4; ++n2) {
            uint32_t bh[4];
            ldsm4(bh, aBh + n2 * (16 * ASTRIDE) + kk * 32);
            mma_f16(acc[2*n2],     ah, bh);
            mma_f16(acc[2*n2 + 1], ah, bh + 2);
        }
    }

    // ---- epilogue in-fragment: bias + LReLU + row-norm; write fp16 ego_out ----
    const float* bs = (const float*)(smem + SM_BS);
    int q  = lane & 3;
    int gr = lane >> 2;
    float ss0 = 0.f, ss1 = 0.f;
    #pragma unroll
    for (int nt = 0; nt < 8; ++nt) {
        float b0 = bs[nt * 8 + 2 * q], b1 = bs[nt * 8 + 2 * q + 1];
        float c0 = acc[nt][0] + b0, c1 = acc[nt][1] + b1;
        float c2 = acc[nt][2] + b0, c3 = acc[nt][3] + b1;
        c0 = c0 > 0.f ? c0 : 0.2f * c0;
        c1 = c1 > 0.f ? c1 : 0.2f * c1;
        c2 = c2 > 0.f ? c2 : 0.2f * c2;
        c3 = c3 > 0.f ? c3 : 0.2f * c3;
        ss0 += c0 * c0 + c1 * c1;
        ss1 += c2 * c2 + c3 * c3;
        acc[nt][0] = c0; acc[nt][1] = c1; acc[nt][2] = c2; acc[nt][3] = c3;
    }
    ss0 += __shfl_xor_sync(0xffffffffu, ss0, 1);
    ss0 += __shfl_xor_sync(0xffffffffu, ss0, 2);
    ss1 += __shfl_xor_sync(0xffffffffu, ss1, 1);
    ss1 += __shfl_xor_sync(0xffffffffu, ss1, 2);
    float sc0 = 1.0f / fmaxf(sqrtf(ss0), 1e-12f);
    float sc1 = 1.0f / fmaxf(sqrtf(ss1), 1e-12f);

    int n0 = base + m0 + gr;
    int n1 = n0 + 8;
    #pragma unroll
    for (int nt = 0; nt < 8; ++nt) {
        int cw = nt * 4 + q;                 // half2 word index (cols 2cw, 2cw+1)
        if (n0 < N_NODES)
            ego_out[(size_t)n0 * 32 + cw] = pack_h2(acc[nt][0] * sc0, acc[nt][1] * sc0);
        if (n1 < N_NODES)
            ego_out[(size_t)n1 * 32 + cw] = pack_h2(acc[nt][2] * sc1, acc[nt][3] * sc1);
    }
}

// ---------------- output: dot(sum_k ego_k[u], sum_k ego_k[i]) / 16 ------------
__global__ __launch_bounds__(256) void out_kernel(const int* __restrict__ users,
                                                  const int* __restrict__ items,
                                                  float* __restrict__ out) {
    int b = blockIdx.x * 8 + (threadIdx.x >> 5);
    int lane = threadIdx.x & 31;
    if (b >= BATCH) return;
    size_t u = (size_t)__ldg(users + b) * 32 + lane;
    size_t i = ((size_t)N_USERS + __ldg(items + b)) * 32 + lane;
    float2 u0 = unpack_h2(g_ego0[u]), u1 = unpack_h2(g_ego1[u]);
    float2 u2 = unpack_h2(g_ego2[u]), u3 = unpack_h2(g_ego3[u]);
    float2 i0 = unpack_h2(g_ego0[i]), i1 = unpack_h2(g_ego1[i]);
    float2 i2 = unpack_h2(g_ego2[i]), i3 = unpack_h2(g_ego3[i]);
    float ux = u0.x + u1.x + u2.x + u3.x;
    float uy = u0.y + u1.y + u2.y + u3.y;
    float ix = i0.x + i1.x + i2.x + i3.x;
    float iy = i0.y + i1.y + i2.y + i3.y;
    float s = ux * ix + uy * iy;
    #pragma unroll
    for (int o = 16; o > 0; o >>= 1) s += __shfl_xor_sync(0xffffffffu, s, o);
    if (lane == 0) out[b] = s * (1.0f / 16.0f);
}

// ---------------- host launcher ------------------------------------------------
extern "C" void kernel_launch(void* const* d_in, const int* in_sizes, int n_in,
                              void* d_out, int out_size) {
    const int*   users    = (const int*)  d_in[0];
    const int*   items    = (const int*)  d_in[1];
    const int*   rows     = (const int*)  d_in[2];
    const int*   cols     = (const int*)  d_in[3];
    const float* vals     = (const float*)d_in[4];
    const float* user_emb = (const float*)d_in[5];
    const float* item_emb = (const float*)d_in[6];
    const float* W_gc     = (const float*)d_in[7];
    const float* b_gc     = (const float*)d_in[8];
    const float* W_bi     = (const float*)d_in[9];
    const float* b_bi     = (const float*)d_in[10];
    float*       out      = (float*)d_out;

    cudaFuncSetAttribute(transform_kernel,
                         cudaFuncAttributeMaxDynamicSharedMemorySize, SMEM_TR);

    uint32_t* ego[4];
    cudaGetSymbolAddress((void**)&ego[0], g_ego0);
    cudaGetSymbolAddress((void**)&ego[1], g_ego1);
    cudaGetSymbolAddress((void**)&ego[2], g_ego2);
    cudaGetSymbolAddress((void**)&ego[3], g_ego3);
    unsigned char* wt = nullptr;  float* bsum = nullptr;
    cudaGetSymbolAddress((void**)&wt, g_wt);
    cudaGetSymbolAddress((void**)&bsum, g_bsum);

    const int egrid = (N_EDGES + 255) / 256;
    const int ngrid = (N_NODES + 255) / 256;

    init_kernel<<<(N_NODES * 8 + 255) / 256, 256>>>((const float4*)user_emb,
                                                    (const float4*)item_emb);
    prep_w_kernel<<<3, 256>>>(W_gc, b_gc, W_bi, b_bi);
    hist_kernel<<<egrid, 256>>>(rows);
    offset_kernel<<<ngrid, 256>>>();
    scatter_kernel<<<egrid, 256>>>(rows, cols, vals);

    const int lgrid = (N_NODES + TTILE - 1) / TTILE;
    const int sgrid = (N_NODES + 31) / 32;
    for (int k = 0; k < 3; ++k) {
        spmm_csr_kernel<<<sgrid, 256>>>(ego[k]);
        transform_kernel<<<lgrid, 256, SMEM_TR>>>(ego[k], ego[k + 1],
            wt + (size_t)k * WT_BYTES, bsum + k * 64);
    }

    out_kernel<<<BATCH / 8, 256>>>(users, items, out);
}